// round 4
// baseline (speedup 1.0000x reference)
#include <cuda_runtime.h>

#define NN   50000
#define EE   800000
#define EP   850000      // EE + NN self loops
#define FDIM 256
#define NHEAD 8
#define HID  32
#define OUTC 16

// ---------------- scratch (device globals; no allocation allowed) ----------------
__device__ __align__(16) int   g_ei[2 * EE];          // normalized int32 edge index
__device__ __align__(16) float g_xl[NN * FDIM];       // layer1 x @ W1
__device__ __align__(16) float g_as1[NN * NHEAD];
__device__ __align__(16) float g_ad1[NN * NHEAD];
__device__ __align__(16) float g_den1[NN * NHEAD];
__device__ __align__(16) float g_w1[EP * NHEAD];      // exp(leaky(e)) per edge,head
__device__ __align__(16) float g_out1[NN * FDIM];     // layer1 aggregate (pre relu/bias)
__device__ __align__(16) float g_y[NN * OUTC];        // layer2 h @ W2
__device__ __align__(16) float g_as2[NN];
__device__ __align__(16) float g_ad2[NN];
__device__ __align__(16) float g_den2[NN];
__device__ __align__(16) float g_w2[EP];
__device__ int g_is64;

// ---------------- helpers ----------------
__device__ __forceinline__ unsigned long long pack2(float x, float y) {
    unsigned long long r;
    asm("mov.b64 %0, {%1, %2};" : "=l"(r) : "f"(x), "f"(y));
    return r;
}
__device__ __forceinline__ float2 unpack2(unsigned long long v) {
    float2 r;
    asm("mov.b64 {%0, %1}, %2;" : "=f"(r.x), "=f"(r.y) : "l"(v));
    return r;
}
// packed dual-FMA (sm_100+ only; ptxas never emits this from C++)
__device__ __forceinline__ void ffma2(unsigned long long& d, unsigned long long a,
                                      unsigned long long b) {
    asm("fma.rn.f32x2 %0, %1, %2, %0;" : "+l"(d) : "l"(a), "l"(b));
}
// vectorized no-return global float reduction (sm_90+)
__device__ __forceinline__ void red4(float* p, float a, float4 v) {
    asm volatile("red.global.add.v4.f32 [%0], {%1, %2, %3, %4};"
                 :: "l"(p), "f"(a * v.x), "f"(a * v.y), "f"(a * v.z), "f"(a * v.w)
                 : "memory");
}

// ---------------- setup kernels ----------------
__global__ void k_zero(float4* dout) {
    int i = blockIdx.x * blockDim.x + threadIdx.x;
    float4 z = make_float4(0.f, 0.f, 0.f, 0.f);
    if (i < NN * FDIM / 4)  ((float4*)g_out1)[i] = z;
    if (i < NN * NHEAD / 4) ((float4*)g_den1)[i] = z;
    if (i < NN / 4)         ((float4*)g_den2)[i] = z;
    if (i < NN * OUTC / 4)  dout[i] = z;
}

// Sniff whether edge_index arrived as int64 or int32: for int64 every odd
// 32-bit word is an upper half == 0 (values < 50000); for int32 those words are
// uniform edge ids, P(all 64 zero) ~ 0.
__global__ void k_detect(const unsigned* ei) {
    if (blockIdx.x == 0 && threadIdx.x == 0) {
        int is64 = 1;
        for (int i = 0; i < 64; i++)
            if (ei[2 * i + 1] != 0u) { is64 = 0; break; }
        g_is64 = is64;
    }
}

__global__ void k_convert(const void* ei) {
    int i = blockIdx.x * blockDim.x + threadIdx.x;
    if (i < 2 * EE) {
        g_ei[i] = g_is64 ? (int)((const long long*)ei)[i]
                         : ((const int*)ei)[i];
    }
}

// ---------------- GEMM1: g_xl = x @ W1  (M=50000, N=256, K=256) ----------------
// 128x64 tile, BK=16, 128 threads, 8x8 per thread, f32x2 packed FMA along N.
#define GM 128
#define GN 64
#define GK 16
__global__ void __launch_bounds__(128) k_gemm1(const float* __restrict__ x,
                                               const float* __restrict__ W) {
    __shared__ __align__(16) float As[GK][GM];   // transposed: As[k][m]
    __shared__ __align__(16) float Bs[GK][GN];
    int tid = threadIdx.x;
    int tx = tid & 7;        // col group 0..7  -> 8 cols each
    int ty = tid >> 3;       // row group 0..15 -> 8 rows each
    int bm = blockIdx.x * GM;
    int bn = blockIdx.y * GN;

    unsigned long long acc[8][4];
#pragma unroll
    for (int i = 0; i < 8; i++)
#pragma unroll
        for (int jp = 0; jp < 4; jp++) acc[i][jp] = 0ULL;

    for (int k0 = 0; k0 < FDIM; k0 += GK) {
        // A tile: 128 rows x 16 k  (512 float4, 4 per thread), store transposed
#pragma unroll
        for (int i = 0; i < 4; i++) {
            int flat = i * 128 + tid;        // 0..511
            int row  = flat >> 2;
            int c4   = flat & 3;
            float4 v = make_float4(0.f, 0.f, 0.f, 0.f);
            int gr = bm + row;
            if (gr < NN) v = *(const float4*)&x[gr * FDIM + k0 + c4 * 4];
            As[c4 * 4 + 0][row] = v.x;
            As[c4 * 4 + 1][row] = v.y;
            As[c4 * 4 + 2][row] = v.z;
            As[c4 * 4 + 3][row] = v.w;
        }
        // B tile: 16 k x 64 n (256 float4, 2 per thread)
#pragma unroll
        for (int i = 0; i < 2; i++) {
            int flat = i * 128 + tid;        // 0..255
            int row  = flat >> 4;
            int c4   = flat & 15;
            *(float4*)&Bs[row][c4 * 4] =
                *(const float4*)&W[(k0 + row) * FDIM + bn + c4 * 4];
        }
        __syncthreads();

#pragma unroll
        for (int kk = 0; kk < GK; kk++) {
            unsigned long long adup[8];
#pragma unroll
            for (int ii = 0; ii < 4; ii++) {
                float2 a = *(const float2*)&As[kk][ty * 8 + ii * 2];
                adup[ii * 2 + 0] = pack2(a.x, a.x);
                adup[ii * 2 + 1] = pack2(a.y, a.y);
            }
            unsigned long long bp[4];
#pragma unroll
            for (int jp = 0; jp < 4; jp++) {
                float2 b = *(const float2*)&Bs[kk][tx * 8 + jp * 2];
                bp[jp] = pack2(b.x, b.y);
            }
#pragma unroll
            for (int i = 0; i < 8; i++)
#pragma unroll
                for (int jp = 0; jp < 4; jp++)
                    ffma2(acc[i][jp], adup[i], bp[jp]);
        }
        __syncthreads();
    }

#pragma unroll
    for (int i = 0; i < 8; i++) {
        int gr = bm + ty * 8 + i;
        if (gr < NN) {
#pragma unroll
            for (int jp = 0; jp < 4; jp++) {
                float2 r = unpack2(acc[i][jp]);
                *(float2*)&g_xl[gr * FDIM + bn + tx * 8 + jp * 2] = r;
            }
        }
    }
}

// ---------------- attention scalar products, layer 1 ----------------
__global__ void __launch_bounds__(256) k_att1(const float* __restrict__ asrc,
                                              const float* __restrict__ adst) {
    int n = blockIdx.x;
    int h = threadIdx.x >> 5;
    int c = threadIdx.x & 31;
    float v = g_xl[n * FDIM + h * HID + c];
    float s = v * __ldg(&asrc[h * HID + c]);
    float d = v * __ldg(&adst[h * HID + c]);
#pragma unroll
    for (int o = 16; o; o >>= 1) {
        s += __shfl_down_sync(0xffffffffu, s, o);
        d += __shfl_down_sync(0xffffffffu, d, o);
    }
    if (c == 0) {
        g_as1[n * NHEAD + h] = s;
        g_ad1[n * NHEAD + h] = d;
    }
}

// ---------------- layer 1: exp weights + denominators ----------------
__global__ void k_expsum1() {
    int t = blockIdx.x * blockDim.x + threadIdx.x;
    if (t >= EP * NHEAD) return;
    int e = t >> 3, h = t & 7;
    int s, d;
    if (e < EE) { s = g_ei[e]; d = g_ei[EE + e]; }
    else        { s = d = e - EE; }
    float ev = g_as1[s * NHEAD + h] + g_ad1[d * NHEAD + h];
    ev = ev >= 0.f ? ev : 0.2f * ev;
    float w = __expf(ev);
    g_w1[t] = w;
    atomicAdd(&g_den1[d * NHEAD + h], w);   // no-return -> RED
}

// ---------------- layer 1: message pass (one warp per edge) ----------------
__global__ void __launch_bounds__(256) k_msg1() {
    int e = blockIdx.x * 8 + (threadIdx.x >> 5);
    int lane = threadIdx.x & 31;
    if (e >= EP) return;
    int s, d;
    if (e < EE) { s = g_ei[e]; d = g_ei[EE + e]; }
    else        { s = d = e - EE; }
    float am = 0.f;
    if (lane < 8)
        am = g_w1[e * 8 + lane] / (g_den1[d * 8 + lane] + 1e-16f);
    float aA = __shfl_sync(0xffffffffu, am, lane >> 3);        // h = lane/8
    float aB = __shfl_sync(0xffffffffu, am, 4 + (lane >> 3));  // h = 4 + lane/8
    const float4* xs = (const float4*)&g_xl[s * FDIM];
    float4 v1 = xs[lane];
    float4 v2 = xs[32 + lane];
    red4(&g_out1[d * FDIM + lane * 4], aA, v1);
    red4(&g_out1[d * FDIM + 128 + lane * 4], aB, v2);
}

// ---------------- layer 2: relu(out1+b1) @ W2, plus att2 dots ----------------
__global__ void __launch_bounds__(256) k_gemm2(const float* __restrict__ b1,
                                               const float* __restrict__ W2,
                                               const float* __restrict__ asrc2,
                                               const float* __restrict__ adst2) {
    __shared__ __align__(16) float W2s[FDIM * 17];   // padded stride 17
    __shared__ float b1s[FDIM];
    __shared__ __align__(16) float hs[8][FDIM];
    int tid = threadIdx.x;
#pragma unroll
    for (int i = 0; i < 16; i++) {
        int idx = i * 256 + tid;                     // 0..4095
        W2s[(idx >> 4) * 17 + (idx & 15)] = W2[idx];
    }
    b1s[tid] = b1[tid];
    __syncthreads();

    int w = tid >> 5, lane = tid & 31;
    int n = blockIdx.x * 8 + w;                      // grid = NN/8 exact
    {
        float4 v1 = *(const float4*)&g_out1[n * FDIM + lane * 4];
        const float* bp = &b1s[lane * 4];
        v1.x = fmaxf(v1.x + bp[0], 0.f);
        v1.y = fmaxf(v1.y + bp[1], 0.f);
        v1.z = fmaxf(v1.z + bp[2], 0.f);
        v1.w = fmaxf(v1.w + bp[3], 0.f);
        *(float4*)&hs[w][lane * 4] = v1;
        float4 v2 = *(const float4*)&g_out1[n * FDIM + 128 + lane * 4];
        const float* bq = &b1s[128 + lane * 4];
        v2.x = fmaxf(v2.x + bq[0], 0.f);
        v2.y = fmaxf(v2.y + bq[1], 0.f);
        v2.z = fmaxf(v2.z + bq[2], 0.f);
        v2.w = fmaxf(v2.w + bq[3], 0.f);
        *(float4*)&hs[w][128 + lane * 4] = v2;
    }
    __syncwarp();
    int c = lane & 15, half = lane >> 4;
    const float* hp = &hs[w][half * 128];
    const float* wp = &W2s[(half * 128) * 17 + c];
    float sum = 0.f;
#pragma unroll 16
    for (int k = 0; k < 128; k++) sum += hp[k] * wp[k * 17];
    sum += __shfl_xor_sync(0xffffffffu, sum, 16);
    if (lane < 16) g_y[n * OUTC + c] = sum;
    float ps = sum * __ldg(&asrc2[c]);
    float pd = sum * __ldg(&adst2[c]);
#pragma unroll
    for (int o = 8; o; o >>= 1) {
        ps += __shfl_xor_sync(0xffffffffu, ps, o);
        pd += __shfl_xor_sync(0xffffffffu, pd, o);
    }
    if (lane == 0) { g_as2[n] = ps; g_ad2[n] = pd; }
}

// ---------------- layer 2: exp weights + denominators ----------------
__global__ void k_expsum2() {
    int t = blockIdx.x * blockDim.x + threadIdx.x;
    if (t >= EP) return;
    int s, d;
    if (t < EE) { s = g_ei[t]; d = g_ei[EE + t]; }
    else        { s = d = t - EE; }
    float ev = g_as2[s] + g_ad2[d];
    ev = ev >= 0.f ? ev : 0.2f * ev;
    float w = __expf(ev);
    g_w2[t] = w;
    atomicAdd(&g_den2[d], w);
}

// ---------------- layer 2: message pass (4 threads per edge) ----------------
__global__ void k_msg2(float* __restrict__ dout) {
    int t = blockIdx.x * blockDim.x + threadIdx.x;
    if (t >= EP * 4) return;
    int e = t >> 2, q = t & 3;
    int s, d;
    if (e < EE) { s = g_ei[e]; d = g_ei[EE + e]; }
    else        { s = d = e - EE; }
    float alpha = g_w2[e] / (g_den2[d] + 1e-16f);
    float4 v = *(const float4*)&g_y[s * OUTC + q * 4];
    red4(&dout[d * OUTC + q * 4], alpha, v);
}

// ---------------- final: +b2 and log_softmax over 16 classes ----------------
__global__ void k_lsm(float* __restrict__ dout, const float* __restrict__ b2) {
    int n = blockIdx.x * blockDim.x + threadIdx.x;
    if (n >= NN) return;
    float v[16];
    const float4* ip = (const float4*)&dout[n * OUTC];
#pragma unroll
    for (int q = 0; q < 4; q++) *(float4*)&v[q * 4] = ip[q];
#pragma unroll
    for (int c = 0; c < 16; c++) v[c] += __ldg(&b2[c]);
    float m = v[0];
#pragma unroll
    for (int c = 1; c < 16; c++) m = fmaxf(m, v[c]);
    float s = 0.f;
#pragma unroll
    for (int c = 0; c < 16; c++) s += __expf(v[c] - m);
    float L = m + __logf(s);
    float4* op = (float4*)&dout[n * OUTC];
#pragma unroll
    for (int q = 0; q < 4; q++) {
        float4 o;
        o.x = v[q * 4 + 0] - L;
        o.y = v[q * 4 + 1] - L;
        o.z = v[q * 4 + 2] - L;
        o.w = v[q * 4 + 3] - L;
        op[q] = o;
    }
}

// ---------------- launch ----------------
extern "C" void kernel_launch(void* const* d_in, const int* in_sizes, int n_in,
                              void* d_out, int out_size) {
    const float* x     = (const float*)d_in[0];
    const void*  ei    = d_in[1];
    const float* W1    = (const float*)d_in[2];
    const float* asr1  = (const float*)d_in[3];
    const float* adr1  = (const float*)d_in[4];
    const float* b1    = (const float*)d_in[5];
    const float* W2    = (const float*)d_in[6];
    const float* asr2  = (const float*)d_in[7];
    const float* adr2  = (const float*)d_in[8];
    const float* b2    = (const float*)d_in[9];
    float* out = (float*)d_out;

    k_zero<<<(NN * FDIM / 4 + 255) / 256, 256>>>((float4*)out);
    k_detect<<<1, 32>>>((const unsigned*)ei);
    k_convert<<<(2 * EE + 255) / 256, 256>>>(ei);

    dim3 g1((NN + GM - 1) / GM, FDIM / GN);
    k_gemm1<<<g1, 128>>>(x, W1);

    k_att1<<<NN, 256>>>(asr1, adr1);
    k_expsum1<<<(EP * NHEAD + 255) / 256, 256>>>();
    k_msg1<<<(EP + 7) / 8, 256>>>();

    k_gemm2<<<NN / 8, 256>>>(b1, W2, asr2, adr2);
    k_expsum2<<<(EP + 255) / 256, 256>>>();
    k_msg2<<<(EP * 4 + 255) / 256, 256>>>(out);

    k_lsm<<<(NN + 127) / 128, 128>>>(out, b2);
}

// round 8
// speedup vs baseline: 1.1250x; 1.1250x over previous
#include <cuda_runtime.h>
#include <cuda_bf16.h>
#include <cstdint>

#define NN   50000
#define EE   800000
#define EP   850000      // EE + NN self loops
#define FDIM 256
#define NHEAD 8
#define HID  32
#define OUTC 16

// ---------------- scratch (device globals; no allocation allowed) ----------------
__device__ __align__(16) int   g_ei[2 * EE];          // normalized int32 edge index
__device__ __align__(16) float g_xl[NN * FDIM];       // layer1 x @ W1
__device__ __align__(16) __nv_bfloat16 g_xh [NN * FDIM];   // bf16 hi of x
__device__ __align__(16) __nv_bfloat16 g_xlo[NN * FDIM];   // bf16 lo of x
__device__ __align__(16) __nv_bfloat16 g_wh [FDIM * FDIM]; // bf16 hi of W1^T [n][k]
__device__ __align__(16) __nv_bfloat16 g_wlo[FDIM * FDIM]; // bf16 lo of W1^T
__device__ __align__(16) float g_as1[NN * NHEAD];
__device__ __align__(16) float g_ad1[NN * NHEAD];
__device__ __align__(16) float g_den1[NN * NHEAD];
__device__ __align__(16) float g_w1[EP * NHEAD];      // exp(leaky(e)) per edge,head
__device__ __align__(16) float g_out1[NN * FDIM];     // layer1 aggregate (pre relu/bias)
__device__ __align__(16) float g_y[NN * OUTC];        // layer2 h @ W2
__device__ __align__(16) float g_as2[NN];
__device__ __align__(16) float g_ad2[NN];
__device__ __align__(16) float g_den2[NN];
__device__ __align__(16) float g_w2[EP];
__device__ int g_is64;

// ---------------- helpers ----------------
__device__ __forceinline__ uint32_t smem_u32(const void* p) {
    uint32_t a;
    asm("{ .reg .u64 t; cvta.to.shared.u64 t, %1; cvt.u32.u64 %0, t; }"
        : "=r"(a) : "l"(p));
    return a;
}
__device__ __forceinline__ void red4(float* p, float a, float4 v) {
    asm volatile("red.global.add.v4.f32 [%0], {%1, %2, %3, %4};"
                 :: "l"(p), "f"(a * v.x), "f"(a * v.y), "f"(a * v.z), "f"(a * v.w)
                 : "memory");
}
__device__ __forceinline__ void ldsm4(uint32_t* r, uint32_t addr) {
    asm volatile("ldmatrix.sync.aligned.m8n8.x4.shared.b16 {%0,%1,%2,%3}, [%4];"
                 : "=r"(r[0]), "=r"(r[1]), "=r"(r[2]), "=r"(r[3]) : "r"(addr));
}
__device__ __forceinline__ void ldsm2(uint32_t* r, uint32_t addr) {
    asm volatile("ldmatrix.sync.aligned.m8n8.x2.shared.b16 {%0,%1}, [%2];"
                 : "=r"(r[0]), "=r"(r[1]) : "r"(addr));
}
__device__ __forceinline__ void mma16816(float* d, const uint32_t* a, const uint32_t* b) {
    asm volatile("mma.sync.aligned.m16n8k16.row.col.f32.bf16.bf16.f32 "
                 "{%0,%1,%2,%3}, {%4,%5,%6,%7}, {%8,%9}, {%0,%1,%2,%3};"
                 : "+f"(d[0]), "+f"(d[1]), "+f"(d[2]), "+f"(d[3])
                 : "r"(a[0]), "r"(a[1]), "r"(a[2]), "r"(a[3]), "r"(b[0]), "r"(b[1]));
}
__device__ __forceinline__ void cpa16(uint32_t dst, const void* src) {
    asm volatile("cp.async.ca.shared.global [%0], [%1], 16;"
                 :: "r"(dst), "l"(src) : "memory");
}

// ---------------- setup kernels ----------------
__global__ void k_zero(float4* dout) {
    int i = blockIdx.x * blockDim.x + threadIdx.x;
    float4 z = make_float4(0.f, 0.f, 0.f, 0.f);
    if (i < NN * FDIM / 4)  ((float4*)g_out1)[i] = z;
    if (i < NN * NHEAD / 4) ((float4*)g_den1)[i] = z;
    if (i < NN / 4)         ((float4*)g_den2)[i] = z;
    if (i < NN * OUTC / 4)  dout[i] = z;
}

__global__ void k_detect(const unsigned* ei) {
    if (blockIdx.x == 0 && threadIdx.x == 0) {
        int is64 = 1;
        for (int i = 0; i < 64; i++)
            if (ei[2 * i + 1] != 0u) { is64 = 0; break; }
        g_is64 = is64;
    }
}

__global__ void k_convert(const void* ei) {
    int i = blockIdx.x * blockDim.x + threadIdx.x;
    if (i < 2 * EE) {
        g_ei[i] = g_is64 ? (int)((const long long*)ei)[i]
                         : ((const int*)ei)[i];
    }
}

// ---------------- bf16 hi/lo split helpers ----------------
__device__ __forceinline__ void split2(float a, float b, unsigned& hi, unsigned& lo) {
    __nv_bfloat16 ha = __float2bfloat16(a), hb = __float2bfloat16(b);
    __nv_bfloat16 la = __float2bfloat16(a - __bfloat162float(ha));
    __nv_bfloat16 lb = __float2bfloat16(b - __bfloat162float(hb));
    __nv_bfloat162 H; H.x = ha; H.y = hb; hi = *(unsigned*)&H;
    __nv_bfloat162 L; L.x = la; L.y = lb; lo = *(unsigned*)&L;
}

__global__ void k_cvt_x(const float* __restrict__ x) {
    int i = blockIdx.x * blockDim.x + threadIdx.x;   // float4 index
    if (i >= NN * FDIM / 4) return;
    float4 v = ((const float4*)x)[i];
    uint2 H, L;
    split2(v.x, v.y, H.x, L.x);
    split2(v.z, v.w, H.y, L.y);
    ((uint2*)g_xh)[i]  = H;
    ((uint2*)g_xlo)[i] = L;
}

// W1 is [K=256, N=256] row-major; produce transposed [n][k] bf16 hi/lo.
__global__ void k_cvt_w(const float* __restrict__ W) {
    int idx = blockIdx.x * blockDim.x + threadIdx.x;  // 32768 threads
    if (idx >= FDIM * FDIM / 2) return;
    int n  = idx >> 7;
    int kk = (idx & 127) * 2;
    float v0 = W[kk * FDIM + n];
    float v1 = W[(kk + 1) * FDIM + n];
    unsigned hi, lo;
    split2(v0, v1, hi, lo);
    *(unsigned*)&g_wh [n * FDIM + kk] = hi;
    *(unsigned*)&g_wlo[n * FDIM + kk] = lo;
}

// ---------------- GEMM1 via mma.sync bf16 (split expressed as K=768) ----------
// g_xl = x @ W1 as AhBh + AlBh + AhBl. Block 128x128, 8 warps (32x64 each),
// BK=32, cp.async double buffer, padded stride 40 (conflict-free ldmatrix).
#define BM 128
#define BN 128
#define BK 32
#define SSTR 40
#define NCH 24            // 768 / 32
#define ABUF (BM * SSTR * 2)   // bytes per buffer

__global__ void __launch_bounds__(256) k_gemm1_mma() {
    __shared__ __align__(16) __nv_bfloat16 As[2][BM][SSTR];
    __shared__ __align__(16) __nv_bfloat16 Bs[2][BN][SSTR];
    int tid = threadIdx.x, lane = tid & 31, wid = tid >> 5;
    int warpM = wid & 3, warpN = wid >> 2;
    int bm = blockIdx.x * BM, bn = blockIdx.y * BN;

    uint32_t asb = smem_u32(&As[0][0][0]);
    uint32_t bsb = smem_u32(&Bs[0][0][0]);

    // per-lane fragment base offsets (bytes)
    uint32_t a_off = (uint32_t)(((warpM * 32 + (lane & 15)) * SSTR + ((lane >> 4) << 3)) * 2);
    uint32_t b_off = (uint32_t)(((warpN * 64 + (lane & 7)) * SSTR + (((lane >> 3) & 1) << 3)) * 2);

    // per-thread cp.async coordinates (2 chunks of 16B for A, 2 for B)
    int rowA0 = tid >> 2,        segA0 = tid & 3;          // flat = tid
    int rowA1 = (256 + tid) >> 2, segA1 = (256 + tid) & 3; // flat = 256+tid
    int grA0 = min(bm + rowA0, NN - 1);
    int grA1 = min(bm + rowA1, NN - 1);

    float acc[2][8][4];
#pragma unroll
    for (int mt = 0; mt < 2; mt++)
#pragma unroll
        for (int nt = 0; nt < 8; nt++)
#pragma unroll
            for (int q = 0; q < 4; q++) acc[mt][nt][q] = 0.f;

    auto fill = [&](int c, int buf) {
        const __nv_bfloat16* Asrc = (c >= 8 && c < 16) ? g_xlo : g_xh;
        const __nv_bfloat16* Bsrc = (c < 16) ? g_wh : g_wlo;
        int kk = (c & 7) * BK;
        uint32_t ad = asb + buf * ABUF;
        uint32_t bd = bsb + buf * ABUF;
        cpa16(ad + (rowA0 * SSTR + segA0 * 8) * 2,
              &Asrc[(size_t)grA0 * FDIM + kk + segA0 * 8]);
        cpa16(ad + (rowA1 * SSTR + segA1 * 8) * 2,
              &Asrc[(size_t)grA1 * FDIM + kk + segA1 * 8]);
        cpa16(bd + (rowA0 * SSTR + segA0 * 8) * 2,
              &Bsrc[(size_t)(bn + rowA0) * FDIM + kk + segA0 * 8]);
        cpa16(bd + (rowA1 * SSTR + segA1 * 8) * 2,
              &Bsrc[(size_t)(bn + rowA1) * FDIM + kk + segA1 * 8]);
        asm volatile("cp.async.commit_group;" ::: "memory");
    };

    fill(0, 0);
    for (int c = 0; c < NCH; c++) {
        int buf = c & 1;
        if (c + 1 < NCH) {
            fill(c + 1, buf ^ 1);
            asm volatile("cp.async.wait_group 1;" ::: "memory");
        } else {
            asm volatile("cp.async.wait_group 0;" ::: "memory");
        }
        __syncthreads();

        uint32_t ab = asb + buf * ABUF + a_off;
        uint32_t bb = bsb + buf * ABUF + b_off;
#pragma unroll
        for (int ks = 0; ks < 2; ks++) {
            uint32_t af[2][4];
            ldsm4(af[0], ab + (ks * 16) * 2);
            ldsm4(af[1], ab + (16 * SSTR + ks * 16) * 2);
            uint32_t bf[8][2];
#pragma unroll
            for (int nt = 0; nt < 8; nt++)
                ldsm2(bf[nt], bb + (nt * 8 * SSTR + ks * 16) * 2);
#pragma unroll
            for (int mt = 0; mt < 2; mt++)
#pragma unroll
                for (int nt = 0; nt < 8; nt++)
                    mma16816(acc[mt][nt], af[mt], bf[nt]);
        }
        __syncthreads();   // protect buf before it is refilled at c+2
    }

    // epilogue: d0,d1 -> (row l/4, col 2*(l%4)); d2,d3 -> row+8
    int rbase = bm + warpM * 32 + (lane >> 2);
    int cbase = bn + warpN * 64 + 2 * (lane & 3);
#pragma unroll
    for (int mt = 0; mt < 2; mt++) {
        int r0 = rbase + mt * 16;
#pragma unroll
        for (int nt = 0; nt < 8; nt++) {
            int cc = cbase + nt * 8;
            if (r0 < NN) {
                float2 v = make_float2(acc[mt][nt][0], acc[mt][nt][1]);
                *(float2*)&g_xl[(size_t)r0 * FDIM + cc] = v;
            }
            if (r0 + 8 < NN) {
                float2 v = make_float2(acc[mt][nt][2], acc[mt][nt][3]);
                *(float2*)&g_xl[(size_t)(r0 + 8) * FDIM + cc] = v;
            }
        }
    }
}

// ---------------- attention scalar products, layer 1 ----------------
__global__ void __launch_bounds__(256) k_att1(const float* __restrict__ asrc,
                                              const float* __restrict__ adst) {
    int n = blockIdx.x;
    int h = threadIdx.x >> 5;
    int c = threadIdx.x & 31;
    float v = g_xl[n * FDIM + h * HID + c];
    float s = v * __ldg(&asrc[h * HID + c]);
    float d = v * __ldg(&adst[h * HID + c]);
#pragma unroll
    for (int o = 16; o; o >>= 1) {
        s += __shfl_down_sync(0xffffffffu, s, o);
        d += __shfl_down_sync(0xffffffffu, d, o);
    }
    if (c == 0) {
        g_as1[n * NHEAD + h] = s;
        g_ad1[n * NHEAD + h] = d;
    }
}

// ---------------- layer 1: exp weights + denominators ----------------
__global__ void k_expsum1() {
    int t = blockIdx.x * blockDim.x + threadIdx.x;
    if (t >= EP * NHEAD) return;
    int e = t >> 3, h = t & 7;
    int s, d;
    if (e < EE) { s = g_ei[e]; d = g_ei[EE + e]; }
    else        { s = d = e - EE; }
    float ev = g_as1[s * NHEAD + h] + g_ad1[d * NHEAD + h];
    ev = ev >= 0.f ? ev : 0.2f * ev;
    float w = __expf(ev);
    g_w1[t] = w;
    atomicAdd(&g_den1[d * NHEAD + h], w);   // no-return -> RED
}

// ---------------- layer 1: message pass (one warp per edge) ----------------
__global__ void __launch_bounds__(256) k_msg1() {
    int e = blockIdx.x * 8 + (threadIdx.x >> 5);
    int lane = threadIdx.x & 31;
    if (e >= EP) return;
    int s, d;
    if (e < EE) { s = g_ei[e]; d = g_ei[EE + e]; }
    else        { s = d = e - EE; }
    float am = 0.f;
    if (lane < 8)
        am = g_w1[e * 8 + lane] / (g_den1[d * 8 + lane] + 1e-16f);
    float aA = __shfl_sync(0xffffffffu, am, lane >> 3);        // h = lane/8
    float aB = __shfl_sync(0xffffffffu, am, 4 + (lane >> 3));  // h = 4 + lane/8
    const float4* xs = (const float4*)&g_xl[s * FDIM];
    float4 v1 = xs[lane];
    float4 v2 = xs[32 + lane];
    red4(&g_out1[d * FDIM + lane * 4], aA, v1);
    red4(&g_out1[d * FDIM + 128 + lane * 4], aB, v2);
}

// ---------------- layer 2: relu(out1+b1) @ W2, plus att2 dots ----------------
__global__ void __launch_bounds__(256) k_gemm2(const float* __restrict__ b1,
                                               const float* __restrict__ W2,
                                               const float* __restrict__ asrc2,
                                               const float* __restrict__ adst2) {
    __shared__ __align__(16) float W2s[FDIM * 17];   // padded stride 17
    __shared__ float b1s[FDIM];
    __shared__ __align__(16) float hs[8][FDIM];
    int tid = threadIdx.x;
#pragma unroll
    for (int i = 0; i < 16; i++) {
        int idx = i * 256 + tid;                     // 0..4095
        W2s[(idx >> 4) * 17 + (idx & 15)] = W2[idx];
    }
    b1s[tid] = b1[tid];
    __syncthreads();

    int w = tid >> 5, lane = tid & 31;
    int n = blockIdx.x * 8 + w;                      // grid = NN/8 exact
    {
        float4 v1 = *(const float4*)&g_out1[n * FDIM + lane * 4];
        const float* bp = &b1s[lane * 4];
        v1.x = fmaxf(v1.x + bp[0], 0.f);
        v1.y = fmaxf(v1.y + bp[1], 0.f);
        v1.z = fmaxf(v1.z + bp[2], 0.f);
        v1.w = fmaxf(v1.w + bp[3], 0.f);
        *(float4*)&hs[w][lane * 4] = v1;
        float4 v2 = *(const float4*)&g_out1[n * FDIM + 128 + lane * 4];
        const float* bq = &b1s[128 + lane * 4];
        v2.x = fmaxf(v2.x + bq[0], 0.f);
        v2.y = fmaxf(v2.y + bq[1], 0.f);
        v2.z = fmaxf(v2.z + bq[2], 0.f);
        v2.w = fmaxf(v2.w + bq[3], 0.f);
        *(float4*)&hs[w][128 + lane * 4] = v2;
    }
    __syncwarp();
    int c = lane & 15, half = lane >> 4;
    const float* hp = &hs[w][half * 128];
    const float* wp = &W2s[(half * 128) * 17 + c];
    float sum = 0.f;
#pragma unroll 16
    for (int k = 0; k < 128; k++) sum += hp[k] * wp[k * 17];
    sum += __shfl_xor_sync(0xffffffffu, sum, 16);
    if (lane < 16) g_y[n * OUTC + c] = sum;
    float ps = sum * __ldg(&asrc2[c]);
    float pd = sum * __ldg(&adst2[c]);
#pragma unroll
    for (int o = 8; o; o >>= 1) {
        ps += __shfl_xor_sync(0xffffffffu, ps, o);
        pd += __shfl_xor_sync(0xffffffffu, pd, o);
    }
    if (lane == 0) { g_as2[n] = ps; g_ad2[n] = pd; }
}

// ---------------- layer 2: exp weights + denominators ----------------
__global__ void k_expsum2() {
    int t = blockIdx.x * blockDim.x + threadIdx.x;
    if (t >= EP) return;
    int s, d;
    if (t < EE) { s = g_ei[t]; d = g_ei[EE + t]; }
    else        { s = d = t - EE; }
    float ev = g_as2[s] + g_ad2[d];
    ev = ev >= 0.f ? ev : 0.2f * ev;
    float w = __expf(ev);
    g_w2[t] = w;
    atomicAdd(&g_den2[d], w);
}

// ---------------- layer 2: message pass (4 threads per edge) ----------------
__global__ void k_msg2(float* __restrict__ dout) {
    int t = blockIdx.x * blockDim.x + threadIdx.x;
    if (t >= EP * 4) return;
    int e = t >> 2, q = t & 3;
    int s, d;
    if (e < EE) { s = g_ei[e]; d = g_ei[EE + e]; }
    else        { s = d = e - EE; }
    float alpha = g_w2[e] / (g_den2[d] + 1e-16f);
    float4 v = *(const float4*)&g_y[s * OUTC + q * 4];
    red4(&dout[d * OUTC + q * 4], alpha, v);
}

// ---------------- final: +b2 and log_softmax over 16 classes ----------------
__global__ void k_lsm(float* __restrict__ dout, const float* __restrict__ b2) {
    int n = blockIdx.x * blockDim.x + threadIdx.x;
    if (n >= NN) return;
    float v[16];
    const float4* ip = (const float4*)&dout[n * OUTC];
#pragma unroll
    for (int q = 0; q < 4; q++) *(float4*)&v[q * 4] = ip[q];
#pragma unroll
    for (int c = 0; c < 16; c++) v[c] += __ldg(&b2[c]);
    float m = v[0];
#pragma unroll
    for (int c = 1; c < 16; c++) m = fmaxf(m, v[c]);
    float s = 0.f;
#pragma unroll
    for (int c = 0; c < 16; c++) s += __expf(v[c] - m);
    float L = m + __logf(s);
    float4* op = (float4*)&dout[n * OUTC];
#pragma unroll
    for (int q = 0; q < 4; q++) {
        float4 o;
        o.x = v[q * 4 + 0] - L;
        o.y = v[q * 4 + 1] - L;
        o.z = v[q * 4 + 2] - L;
        o.w = v[q * 4 + 3] - L;
        op[q] = o;
    }
}

// ---------------- launch ----------------
extern "C" void kernel_launch(void* const* d_in, const int* in_sizes, int n_in,
                              void* d_out, int out_size) {
    const float* x     = (const float*)d_in[0];
    const void*  ei    = d_in[1];
    const float* W1    = (const float*)d_in[2];
    const float* asr1  = (const float*)d_in[3];
    const float* adr1  = (const float*)d_in[4];
    const float* b1    = (const float*)d_in[5];
    const float* W2    = (const float*)d_in[6];
    const float* asr2  = (const float*)d_in[7];
    const float* adr2  = (const float*)d_in[8];
    const float* b2    = (const float*)d_in[9];
    float* out = (float*)d_out;

    k_zero<<<(NN * FDIM / 4 + 255) / 256, 256>>>((float4*)out);
    k_detect<<<1, 32>>>((const unsigned*)ei);
    k_convert<<<(2 * EE + 255) / 256, 256>>>(ei);

    k_cvt_x<<<(NN * FDIM / 4 + 255) / 256, 256>>>(x);
    k_cvt_w<<<(FDIM * FDIM / 2 + 255) / 256, 256>>>(W1);

    dim3 g1((NN + BM - 1) / BM, FDIM / BN);
    k_gemm1_mma<<<g1, 256>>>();

    k_att1<<<NN, 256>>>(asr1, adr1);
    k_expsum1<<<(EP * NHEAD + 255) / 256, 256>>>();
    k_msg1<<<(EP + 7) / 8, 256>>>();

    k_gemm2<<<NN / 8, 256>>>(b1, W2, asr2, adr2);
    k_expsum2<<<(EP + 255) / 256, 256>>>();
    k_msg2<<<(EP * 4 + 255) / 256, 256>>>(out);

    k_lsm<<<(NN + 127) / 128, 128>>>(out, b2);
}

// round 9
// speedup vs baseline: 1.5823x; 1.4065x over previous
#include <cuda_runtime.h>
#include <cuda_bf16.h>
#include <cstdint>

#define NN   50000
#define EE   800000
#define FDIM 256
#define NHEAD 8
#define HID  32
#define OUTC 16
#define NBLK 196          // ceil(NN/256)

// ---------------- scratch (device globals; no allocation allowed) ----------------
__device__ __align__(16) int   g_ei[2 * EE];          // normalized int32 edge index
__device__ __align__(16) float g_xl[NN * FDIM];       // layer1 x @ W1
__device__ __align__(16) __nv_bfloat16 g_xh [NN * FDIM];   // bf16 hi of x
__device__ __align__(16) __nv_bfloat16 g_xlo[NN * FDIM];   // bf16 lo of x
__device__ __align__(16) __nv_bfloat16 g_wh [FDIM * FDIM]; // bf16 hi of W1^T [n][k]
__device__ __align__(16) __nv_bfloat16 g_wlo[FDIM * FDIM]; // bf16 lo of W1^T
__device__ __align__(16) float g_as1[NN * NHEAD];
__device__ __align__(16) float g_ad1[NN * NHEAD];
__device__ __align__(16) float g_out1[NN * FDIM];     // layer1 aggregate (pre relu/bias)
__device__ __align__(16) float g_y[NN * OUTC];        // layer2 h @ W2
__device__ __align__(16) float g_as2[NN];
__device__ __align__(16) float g_ad2[NN];
// CSR by dst (real edges only; self loop handled implicitly)
__device__ int g_cnt[NN];
__device__ int g_start[NN];
__device__ int g_cur[NN];
__device__ int g_csrc[EE];
__device__ int g_bsum[256];
__device__ int g_bpre[256];
__device__ int g_is64;

// ---------------- helpers ----------------
__device__ __forceinline__ uint32_t smem_u32(const void* p) {
    uint32_t a;
    asm("{ .reg .u64 t; cvta.to.shared.u64 t, %1; cvt.u32.u64 %0, t; }"
        : "=r"(a) : "l"(p));
    return a;
}
__device__ __forceinline__ void ldsm4(uint32_t* r, uint32_t addr) {
    asm volatile("ldmatrix.sync.aligned.m8n8.x4.shared.b16 {%0,%1,%2,%3}, [%4];"
                 : "=r"(r[0]), "=r"(r[1]), "=r"(r[2]), "=r"(r[3]) : "r"(addr));
}
__device__ __forceinline__ void ldsm2(uint32_t* r, uint32_t addr) {
    asm volatile("ldmatrix.sync.aligned.m8n8.x2.shared.b16 {%0,%1}, [%2];"
                 : "=r"(r[0]), "=r"(r[1]) : "r"(addr));
}
__device__ __forceinline__ void mma16816(float* d, const uint32_t* a, const uint32_t* b) {
    asm volatile("mma.sync.aligned.m16n8k16.row.col.f32.bf16.bf16.f32 "
                 "{%0,%1,%2,%3}, {%4,%5,%6,%7}, {%8,%9}, {%0,%1,%2,%3};"
                 : "+f"(d[0]), "+f"(d[1]), "+f"(d[2]), "+f"(d[3])
                 : "r"(a[0]), "r"(a[1]), "r"(a[2]), "r"(a[3]), "r"(b[0]), "r"(b[1]));
}
__device__ __forceinline__ void cpa16(uint32_t dst, const void* src) {
    asm volatile("cp.async.ca.shared.global [%0], [%1], 16;"
                 :: "r"(dst), "l"(src) : "memory");
}

// ---------------- setup kernels ----------------
__global__ void k_detect(const unsigned* ei) {
    if (blockIdx.x == 0 && threadIdx.x == 0) {
        int is64 = 1;
        for (int i = 0; i < 64; i++)
            if (ei[2 * i + 1] != 0u) { is64 = 0; break; }
        g_is64 = is64;
    }
}

__global__ void k_convert(const void* ei) {
    int i = blockIdx.x * blockDim.x + threadIdx.x;
    if (i < 2 * EE) {
        g_ei[i] = g_is64 ? (int)((const long long*)ei)[i]
                         : ((const int*)ei)[i];
    }
}

// ---------------- CSR build: histogram -> scan -> scatter ----------------
__global__ void k_init() {
    int i = blockIdx.x * blockDim.x + threadIdx.x;
    if (i < NN) g_cnt[i] = 0;
}
__global__ void k_hist() {
    int e = blockIdx.x * blockDim.x + threadIdx.x;
    if (e < EE) atomicAdd(&g_cnt[g_ei[EE + e]], 1);
}
__global__ void k_scanA() {
    int i = blockIdx.x * 256 + threadIdx.x;
    int v = (i < NN) ? g_cnt[i] : 0;
#pragma unroll
    for (int o = 16; o; o >>= 1) v += __shfl_down_sync(0xffffffffu, v, o);
    __shared__ int s[8];
    if ((threadIdx.x & 31) == 0) s[threadIdx.x >> 5] = v;
    __syncthreads();
    if (threadIdx.x < 8) {
        int t = s[threadIdx.x];
#pragma unroll
        for (int o = 4; o; o >>= 1) t += __shfl_down_sync(0xffu, t, o);
        if (threadIdx.x == 0) g_bsum[blockIdx.x] = t;
    }
}
__global__ void k_scanB() {
    __shared__ int s[256];
    int t = threadIdx.x;
    int v = (t < NBLK) ? g_bsum[t] : 0;
    s[t] = v;
    __syncthreads();
    for (int o = 1; o < 256; o <<= 1) {
        int u = (t >= o) ? s[t - o] : 0;
        __syncthreads();
        s[t] += u;
        __syncthreads();
    }
    if (t < NBLK) g_bpre[t] = s[t] - v;
}
__global__ void k_scanC() {
    __shared__ int s[256];
    int t = threadIdx.x, i = blockIdx.x * 256 + t;
    int v = (i < NN) ? g_cnt[i] : 0;
    s[t] = v;
    __syncthreads();
    for (int o = 1; o < 256; o <<= 1) {
        int u = (t >= o) ? s[t - o] : 0;
        __syncthreads();
        s[t] += u;
        __syncthreads();
    }
    int excl = s[t] - v + g_bpre[blockIdx.x];
    if (i < NN) { g_start[i] = excl; g_cur[i] = excl; }
}
__global__ void k_scatter() {
    int e = blockIdx.x * blockDim.x + threadIdx.x;
    if (e < EE) {
        int d = g_ei[EE + e];
        int p = atomicAdd(&g_cur[d], 1);
        g_csrc[p] = g_ei[e];
    }
}

// ---------------- bf16 hi/lo split helpers ----------------
__device__ __forceinline__ void split2(float a, float b, unsigned& hi, unsigned& lo) {
    __nv_bfloat16 ha = __float2bfloat16(a), hb = __float2bfloat16(b);
    __nv_bfloat16 la = __float2bfloat16(a - __bfloat162float(ha));
    __nv_bfloat16 lb = __float2bfloat16(b - __bfloat162float(hb));
    __nv_bfloat162 H; H.x = ha; H.y = hb; hi = *(unsigned*)&H;
    __nv_bfloat162 L; L.x = la; L.y = lb; lo = *(unsigned*)&L;
}

__global__ void k_cvt_x(const float* __restrict__ x) {
    int i = blockIdx.x * blockDim.x + threadIdx.x;   // float4 index
    if (i >= NN * FDIM / 4) return;
    float4 v = ((const float4*)x)[i];
    uint2 H, L;
    split2(v.x, v.y, H.x, L.x);
    split2(v.z, v.w, H.y, L.y);
    ((uint2*)g_xh)[i]  = H;
    ((uint2*)g_xlo)[i] = L;
}

// W1 is [K=256, N=256] row-major; produce transposed [n][k] bf16 hi/lo.
__global__ void k_cvt_w(const float* __restrict__ W) {
    int idx = blockIdx.x * blockDim.x + threadIdx.x;  // 32768 threads
    if (idx >= FDIM * FDIM / 2) return;
    int n  = idx >> 7;
    int kk = (idx & 127) * 2;
    float v0 = W[kk * FDIM + n];
    float v1 = W[(kk + 1) * FDIM + n];
    unsigned hi, lo;
    split2(v0, v1, hi, lo);
    *(unsigned*)&g_wh [n * FDIM + kk] = hi;
    *(unsigned*)&g_wlo[n * FDIM + kk] = lo;
}

// ---------------- GEMM1 via mma.sync bf16 (split expressed as K=768) ----------
#define BM 128
#define BN 128
#define BK 32
#define SSTR 40
#define NCH 24            // 768 / 32
#define ABUF (BM * SSTR * 2)   // bytes per buffer

__global__ void __launch_bounds__(256) k_gemm1_mma() {
    __shared__ __align__(16) __nv_bfloat16 As[2][BM][SSTR];
    __shared__ __align__(16) __nv_bfloat16 Bs[2][BN][SSTR];
    int tid = threadIdx.x, lane = tid & 31, wid = tid >> 5;
    int warpM = wid & 3, warpN = wid >> 2;
    int bm = blockIdx.x * BM, bn = blockIdx.y * BN;

    uint32_t asb = smem_u32(&As[0][0][0]);
    uint32_t bsb = smem_u32(&Bs[0][0][0]);

    uint32_t a_off = (uint32_t)(((warpM * 32 + (lane & 15)) * SSTR + ((lane >> 4) << 3)) * 2);
    uint32_t b_off = (uint32_t)(((warpN * 64 + (lane & 7)) * SSTR + (((lane >> 3) & 1) << 3)) * 2);

    int rowA0 = tid >> 2,         segA0 = tid & 3;
    int rowA1 = (256 + tid) >> 2, segA1 = (256 + tid) & 3;
    int grA0 = min(bm + rowA0, NN - 1);
    int grA1 = min(bm + rowA1, NN - 1);

    float acc[2][8][4];
#pragma unroll
    for (int mt = 0; mt < 2; mt++)
#pragma unroll
        for (int nt = 0; nt < 8; nt++)
#pragma unroll
            for (int q = 0; q < 4; q++) acc[mt][nt][q] = 0.f;

    auto fill = [&](int c, int buf) {
        const __nv_bfloat16* Asrc = (c >= 8 && c < 16) ? g_xlo : g_xh;
        const __nv_bfloat16* Bsrc = (c < 16) ? g_wh : g_wlo;
        int kk = (c & 7) * BK;
        uint32_t ad = asb + buf * ABUF;
        uint32_t bd = bsb + buf * ABUF;
        cpa16(ad + (rowA0 * SSTR + segA0 * 8) * 2,
              &Asrc[(size_t)grA0 * FDIM + kk + segA0 * 8]);
        cpa16(ad + (rowA1 * SSTR + segA1 * 8) * 2,
              &Asrc[(size_t)grA1 * FDIM + kk + segA1 * 8]);
        cpa16(bd + (rowA0 * SSTR + segA0 * 8) * 2,
              &Bsrc[(size_t)(bn + rowA0) * FDIM + kk + segA0 * 8]);
        cpa16(bd + (rowA1 * SSTR + segA1 * 8) * 2,
              &Bsrc[(size_t)(bn + rowA1) * FDIM + kk + segA1 * 8]);
        asm volatile("cp.async.commit_group;" ::: "memory");
    };

    fill(0, 0);
    for (int c = 0; c < NCH; c++) {
        int buf = c & 1;
        if (c + 1 < NCH) {
            fill(c + 1, buf ^ 1);
            asm volatile("cp.async.wait_group 1;" ::: "memory");
        } else {
            asm volatile("cp.async.wait_group 0;" ::: "memory");
        }
        __syncthreads();

        uint32_t ab = asb + buf * ABUF + a_off;
        uint32_t bb = bsb + buf * ABUF + b_off;
#pragma unroll
        for (int ks = 0; ks < 2; ks++) {
            uint32_t af[2][4];
            ldsm4(af[0], ab + (ks * 16) * 2);
            ldsm4(af[1], ab + (16 * SSTR + ks * 16) * 2);
            uint32_t bf[8][2];
#pragma unroll
            for (int nt = 0; nt < 8; nt++)
                ldsm2(bf[nt], bb + (nt * 8 * SSTR + ks * 16) * 2);
#pragma unroll
            for (int mt = 0; mt < 2; mt++)
#pragma unroll
                for (int nt = 0; nt < 8; nt++)
                    mma16816(acc[mt][nt], af[mt], bf[nt]);
        }
        __syncthreads();
    }

    int rbase = bm + warpM * 32 + (lane >> 2);
    int cbase = bn + warpN * 64 + 2 * (lane & 3);
#pragma unroll
    for (int mt = 0; mt < 2; mt++) {
        int r0 = rbase + mt * 16;
#pragma unroll
        for (int nt = 0; nt < 8; nt++) {
            int cc = cbase + nt * 8;
            if (r0 < NN) {
                float2 v = make_float2(acc[mt][nt][0], acc[mt][nt][1]);
                *(float2*)&g_xl[(size_t)r0 * FDIM + cc] = v;
            }
            if (r0 + 8 < NN) {
                float2 v = make_float2(acc[mt][nt][2], acc[mt][nt][3]);
                *(float2*)&g_xl[(size_t)(r0 + 8) * FDIM + cc] = v;
            }
        }
    }
}

// ---------------- attention scalar products, layer 1 ----------------
__global__ void __launch_bounds__(256) k_att1(const float* __restrict__ asrc,
                                              const float* __restrict__ adst) {
    int n = blockIdx.x;
    int h = threadIdx.x >> 5;
    int c = threadIdx.x & 31;
    float v = g_xl[n * FDIM + h * HID + c];
    float s = v * __ldg(&asrc[h * HID + c]);
    float d = v * __ldg(&adst[h * HID + c]);
#pragma unroll
    for (int o = 16; o; o >>= 1) {
        s += __shfl_down_sync(0xffffffffu, s, o);
        d += __shfl_down_sync(0xffffffffu, d, o);
    }
    if (c == 0) {
        g_as1[n * NHEAD + h] = s;
        g_ad1[n * NHEAD + h] = d;
    }
}

// ---------------- layer 1: fused softmax + aggregation (one warp per dst) ----
__global__ void __launch_bounds__(256) k_agg1() {
    int d = blockIdx.x * 8 + (threadIdx.x >> 5);
    int lane = threadIdx.x & 31;
    if (d >= NN) return;

    float ad = (lane < 8) ? g_ad1[d * NHEAD + lane] : 0.f;
    float wsum = 0.f;
    float4 accA = make_float4(0.f, 0.f, 0.f, 0.f);
    float4 accB = make_float4(0.f, 0.f, 0.f, 0.f);

    int beg = g_start[d];
    int end = beg + g_cnt[d];
    for (int p = beg - 1; p < end; p++) {       // p==beg-1 -> self loop
        int s = (p < beg) ? d : g_csrc[p];
        float w = 0.f;
        if (lane < 8) {
            float ev = g_as1[s * NHEAD + lane] + ad;
            ev = ev >= 0.f ? ev : 0.2f * ev;
            w = __expf(ev);
            wsum += w;
        }
        float aA = __shfl_sync(0xffffffffu, w, lane >> 3);        // head lane/8
        float aB = __shfl_sync(0xffffffffu, w, 4 + (lane >> 3));  // head 4+lane/8
        const float4* xs = (const float4*)&g_xl[(size_t)s * FDIM];
        float4 v1 = xs[lane];
        float4 v2 = xs[32 + lane];
        accA.x = fmaf(aA, v1.x, accA.x);
        accA.y = fmaf(aA, v1.y, accA.y);
        accA.z = fmaf(aA, v1.z, accA.z);
        accA.w = fmaf(aA, v1.w, accA.w);
        accB.x = fmaf(aB, v2.x, accB.x);
        accB.y = fmaf(aB, v2.y, accB.y);
        accB.z = fmaf(aB, v2.z, accB.z);
        accB.w = fmaf(aB, v2.w, accB.w);
    }
    float dA = __shfl_sync(0xffffffffu, wsum, lane >> 3);
    float dB = __shfl_sync(0xffffffffu, wsum, 4 + (lane >> 3));
    float rA = 1.f / (dA + 1e-16f);
    float rB = 1.f / (dB + 1e-16f);
    accA.x *= rA; accA.y *= rA; accA.z *= rA; accA.w *= rA;
    accB.x *= rB; accB.y *= rB; accB.z *= rB; accB.w *= rB;
    *(float4*)&g_out1[(size_t)d * FDIM + lane * 4] = accA;
    *(float4*)&g_out1[(size_t)d * FDIM + 128 + lane * 4] = accB;
}

// ---------------- layer 2: relu(out1+b1) @ W2, plus att2 dots ----------------
__global__ void __launch_bounds__(256) k_gemm2(const float* __restrict__ b1,
                                               const float* __restrict__ W2,
                                               const float* __restrict__ asrc2,
                                               const float* __restrict__ adst2) {
    __shared__ __align__(16) float W2s[FDIM * 17];   // padded stride 17
    __shared__ float b1s[FDIM];
    __shared__ __align__(16) float hs[8][FDIM];
    int tid = threadIdx.x;
#pragma unroll
    for (int i = 0; i < 16; i++) {
        int idx = i * 256 + tid;                     // 0..4095
        W2s[(idx >> 4) * 17 + (idx & 15)] = W2[idx];
    }
    b1s[tid] = b1[tid];
    __syncthreads();

    int w = tid >> 5, lane = tid & 31;
    int n = blockIdx.x * 8 + w;                      // grid = NN/8 exact
    {
        float4 v1 = *(const float4*)&g_out1[n * FDIM + lane * 4];
        const float* bp = &b1s[lane * 4];
        v1.x = fmaxf(v1.x + bp[0], 0.f);
        v1.y = fmaxf(v1.y + bp[1], 0.f);
        v1.z = fmaxf(v1.z + bp[2], 0.f);
        v1.w = fmaxf(v1.w + bp[3], 0.f);
        *(float4*)&hs[w][lane * 4] = v1;
        float4 v2 = *(const float4*)&g_out1[n * FDIM + 128 + lane * 4];
        const float* bq = &b1s[128 + lane * 4];
        v2.x = fmaxf(v2.x + bq[0], 0.f);
        v2.y = fmaxf(v2.y + bq[1], 0.f);
        v2.z = fmaxf(v2.z + bq[2], 0.f);
        v2.w = fmaxf(v2.w + bq[3], 0.f);
        *(float4*)&hs[w][128 + lane * 4] = v2;
    }
    __syncwarp();
    int c = lane & 15, half = lane >> 4;
    const float* hp = &hs[w][half * 128];
    const float* wp = &W2s[(half * 128) * 17 + c];
    float sum = 0.f;
#pragma unroll 16
    for (int k = 0; k < 128; k++) sum += hp[k] * wp[k * 17];
    sum += __shfl_xor_sync(0xffffffffu, sum, 16);
    if (lane < 16) g_y[n * OUTC + c] = sum;
    float ps = sum * __ldg(&asrc2[c]);
    float pd = sum * __ldg(&adst2[c]);
#pragma unroll
    for (int o = 8; o; o >>= 1) {
        ps += __shfl_xor_sync(0xffffffffu, ps, o);
        pd += __shfl_xor_sync(0xffffffffu, pd, o);
    }
    if (lane == 0) { g_as2[n] = ps; g_ad2[n] = pd; }
}

// ---------------- layer 2: fused softmax-agg + bias + log_softmax ------------
// One 16-lane half-warp per dst node.
__global__ void __launch_bounds__(256) k_agg2(float* __restrict__ dout,
                                              const float* __restrict__ b2) {
    int d = blockIdx.x * 16 + (threadIdx.x >> 4);
    int c = threadIdx.x & 15;
    if (d >= NN) return;

    float ad = g_ad2[d];
    float acc = 0.f, wsum = 0.f;
    int beg = g_start[d];
    int end = beg + g_cnt[d];
    for (int p = beg - 1; p < end; p++) {
        int s = (p < beg) ? d : g_csrc[p];
        float ev = g_as2[s] + ad;
        ev = ev >= 0.f ? ev : 0.2f * ev;
        float w = __expf(ev);
        wsum += w;
        acc = fmaf(w, g_y[s * OUTC + c], acc);
    }
    float v = acc / (wsum + 1e-16f) + __ldg(&b2[c]);

    float m = v;
#pragma unroll
    for (int o = 8; o; o >>= 1)
        m = fmaxf(m, __shfl_xor_sync(0xffffffffu, m, o, 16));
    float ex = __expf(v - m);
    float ssum = ex;
#pragma unroll
    for (int o = 8; o; o >>= 1)
        ssum += __shfl_xor_sync(0xffffffffu, ssum, o, 16);
    dout[d * OUTC + c] = v - m - __logf(ssum);
}

// ---------------- launch ----------------
extern "C" void kernel_launch(void* const* d_in, const int* in_sizes, int n_in,
                              void* d_out, int out_size) {
    const float* x     = (const float*)d_in[0];
    const void*  ei    = d_in[1];
    const float* W1    = (const float*)d_in[2];
    const float* asr1  = (const float*)d_in[3];
    const float* adr1  = (const float*)d_in[4];
    const float* b1    = (const float*)d_in[5];
    const float* W2    = (const float*)d_in[6];
    const float* asr2  = (const float*)d_in[7];
    const float* adr2  = (const float*)d_in[8];
    const float* b2    = (const float*)d_in[9];
    float* out = (float*)d_out;

    k_detect<<<1, 32>>>((const unsigned*)ei);
    k_convert<<<(2 * EE + 255) / 256, 256>>>(ei);

    // CSR build
    k_init<<<NBLK, 256>>>();
    k_hist<<<(EE + 255) / 256, 256>>>();
    k_scanA<<<NBLK, 256>>>();
    k_scanB<<<1, 256>>>();
    k_scanC<<<NBLK, 256>>>();
    k_scatter<<<(EE + 255) / 256, 256>>>();

    // bf16 split + GEMM1 + att1
    k_cvt_x<<<(NN * FDIM / 4 + 255) / 256, 256>>>(x);
    k_cvt_w<<<(FDIM * FDIM / 2 + 255) / 256, 256>>>(W1);
    dim3 g1((NN + BM - 1) / BM, FDIM / BN);
    k_gemm1_mma<<<g1, 256>>>();
    k_att1<<<NN, 256>>>(asr1, adr1);

    // layer 1 edge aggregation (gather-only)
    k_agg1<<<(NN + 7) / 8, 256>>>();

    // layer 2
    k_gemm2<<<NN / 8, 256>>>(b1, W2, asr2, adr2);
    k_agg2<<<(NN + 15) / 16, 256>>>(out, b2);
}

// round 10
// speedup vs baseline: 1.6970x; 1.0725x over previous
#include <cuda_runtime.h>
#include <cuda_bf16.h>
#include <cstdint>

#define NN   50000
#define EE   800000
#define FDIM 256
#define NHEAD 8
#define HID  32
#define OUTC 16
#define NBLK 196          // ceil(NN/256)

// ---------------- scratch (device globals; no allocation allowed) ----------------
__device__ __align__(16) int   g_ei[2 * EE];          // normalized int32 edge index
__device__ __align__(16) float g_xl[NN * FDIM];       // layer1 x @ W1
__device__ __align__(16) __nv_bfloat16 g_xh [NN * FDIM];   // bf16 hi of x
__device__ __align__(16) __nv_bfloat16 g_xlo[NN * FDIM];   // bf16 lo of x
__device__ __align__(16) __nv_bfloat16 g_wh [FDIM * FDIM]; // bf16 hi of W1^T [n][k]
__device__ __align__(16) __nv_bfloat16 g_wlo[FDIM * FDIM]; // bf16 lo of W1^T
__device__ __align__(16) float g_as1[NN * NHEAD];
__device__ __align__(16) float g_ad1[NN * NHEAD];
__device__ __align__(16) float g_out1[NN * FDIM];     // layer1 aggregate (pre relu/bias)
__device__ __align__(16) float g_y[NN * OUTC];        // layer2 h @ W2
__device__ __align__(16) float g_as2[NN];
__device__ __align__(16) float g_ad2[NN];
// CSR by dst (real edges only; self loop handled implicitly)
__device__ int g_cnt[NN];
__device__ int g_start[NN];
__device__ int g_cur[NN];
__device__ int g_csrc[EE];
__device__ int g_bsum[256];
__device__ int g_bpre[256];
__device__ int g_is64;

// ---------------- helpers ----------------
__device__ __forceinline__ uint32_t smem_u32(const void* p) {
    uint32_t a;
    asm("{ .reg .u64 t; cvta.to.shared.u64 t, %1; cvt.u32.u64 %0, t; }"
        : "=r"(a) : "l"(p));
    return a;
}
__device__ __forceinline__ void ldsm4(uint32_t* r, uint32_t addr) {
    asm volatile("ldmatrix.sync.aligned.m8n8.x4.shared.b16 {%0,%1,%2,%3}, [%4];"
                 : "=r"(r[0]), "=r"(r[1]), "=r"(r[2]), "=r"(r[3]) : "r"(addr));
}
__device__ __forceinline__ void ldsm2(uint32_t* r, uint32_t addr) {
    asm volatile("ldmatrix.sync.aligned.m8n8.x2.shared.b16 {%0,%1}, [%2];"
                 : "=r"(r[0]), "=r"(r[1]) : "r"(addr));
}
__device__ __forceinline__ void mma16816(float* d, const uint32_t* a, const uint32_t* b) {
    asm volatile("mma.sync.aligned.m16n8k16.row.col.f32.bf16.bf16.f32 "
                 "{%0,%1,%2,%3}, {%4,%5,%6,%7}, {%8,%9}, {%0,%1,%2,%3};"
                 : "+f"(d[0]), "+f"(d[1]), "+f"(d[2]), "+f"(d[3])
                 : "r"(a[0]), "r"(a[1]), "r"(a[2]), "r"(a[3]), "r"(b[0]), "r"(b[1]));
}
__device__ __forceinline__ void cpa16(uint32_t dst, const void* src) {
    asm volatile("cp.async.ca.shared.global [%0], [%1], 16;"
                 :: "r"(dst), "l"(src) : "memory");
}

// ---------------- setup kernels ----------------
__global__ void k_detect(const unsigned* ei) {
    if (blockIdx.x == 0 && threadIdx.x == 0) {
        int is64 = 1;
        for (int i = 0; i < 64; i++)
            if (ei[2 * i + 1] != 0u) { is64 = 0; break; }
        g_is64 = is64;
    }
}

__global__ void k_init() {
    int i = blockIdx.x * blockDim.x + threadIdx.x;
    if (i < NN) g_cnt[i] = 0;
}

// convert edge index to int32 AND histogram dst counts in one pass
__global__ void k_convert_hist(const void* ei) {
    int i = blockIdx.x * blockDim.x + threadIdx.x;
    if (i < 2 * EE) {
        int v = g_is64 ? (int)((const long long*)ei)[i]
                       : ((const int*)ei)[i];
        g_ei[i] = v;
        if (i >= EE) atomicAdd(&g_cnt[v], 1);
    }
}

// ---------------- CSR build: scan -> scatter ----------------
__global__ void k_scanA() {
    int i = blockIdx.x * 256 + threadIdx.x;
    int v = (i < NN) ? g_cnt[i] : 0;
#pragma unroll
    for (int o = 16; o; o >>= 1) v += __shfl_down_sync(0xffffffffu, v, o);
    __shared__ int s[8];
    if ((threadIdx.x & 31) == 0) s[threadIdx.x >> 5] = v;
    __syncthreads();
    if (threadIdx.x < 8) {
        int t = s[threadIdx.x];
#pragma unroll
        for (int o = 4; o; o >>= 1) t += __shfl_down_sync(0xffu, t, o);
        if (threadIdx.x == 0) g_bsum[blockIdx.x] = t;
    }
}
__global__ void k_scanB() {
    __shared__ int s[256];
    int t = threadIdx.x;
    int v = (t < NBLK) ? g_bsum[t] : 0;
    s[t] = v;
    __syncthreads();
    for (int o = 1; o < 256; o <<= 1) {
        int u = (t >= o) ? s[t - o] : 0;
        __syncthreads();
        s[t] += u;
        __syncthreads();
    }
    if (t < NBLK) g_bpre[t] = s[t] - v;
}
__global__ void k_scanC() {
    __shared__ int s[256];
    int t = threadIdx.x, i = blockIdx.x * 256 + t;
    int v = (i < NN) ? g_cnt[i] : 0;
    s[t] = v;
    __syncthreads();
    for (int o = 1; o < 256; o <<= 1) {
        int u = (t >= o) ? s[t - o] : 0;
        __syncthreads();
        s[t] += u;
        __syncthreads();
    }
    int excl = s[t] - v + g_bpre[blockIdx.x];
    if (i < NN) { g_start[i] = excl; g_cur[i] = excl; }
}
__global__ void k_scatter() {
    int e = blockIdx.x * blockDim.x + threadIdx.x;
    if (e < EE) {
        int d = g_ei[EE + e];
        int p = atomicAdd(&g_cur[d], 1);
        g_csrc[p] = g_ei[e];
    }
}

// ---------------- bf16 hi/lo split helpers ----------------
__device__ __forceinline__ void split2(float a, float b, unsigned& hi, unsigned& lo) {
    __nv_bfloat16 ha = __float2bfloat16(a), hb = __float2bfloat16(b);
    __nv_bfloat16 la = __float2bfloat16(a - __bfloat162float(ha));
    __nv_bfloat16 lb = __float2bfloat16(b - __bfloat162float(hb));
    __nv_bfloat162 H; H.x = ha; H.y = hb; hi = *(unsigned*)&H;
    __nv_bfloat162 L; L.x = la; L.y = lb; lo = *(unsigned*)&L;
}

__global__ void k_cvt_x(const float* __restrict__ x) {
    int i = blockIdx.x * blockDim.x + threadIdx.x;   // float4 index
    if (i >= NN * FDIM / 4) return;
    float4 v = ((const float4*)x)[i];
    uint2 H, L;
    split2(v.x, v.y, H.x, L.x);
    split2(v.z, v.w, H.y, L.y);
    ((uint2*)g_xh)[i]  = H;
    ((uint2*)g_xlo)[i] = L;
}

// W1 is [K=256, N=256] row-major; produce transposed [n][k] bf16 hi/lo.
__global__ void k_cvt_w(const float* __restrict__ W) {
    int idx = blockIdx.x * blockDim.x + threadIdx.x;  // 32768 threads
    if (idx >= FDIM * FDIM / 2) return;
    int n  = idx >> 7;
    int kk = (idx & 127) * 2;
    float v0 = W[kk * FDIM + n];
    float v1 = W[(kk + 1) * FDIM + n];
    unsigned hi, lo;
    split2(v0, v1, hi, lo);
    *(unsigned*)&g_wh [n * FDIM + kk] = hi;
    *(unsigned*)&g_wlo[n * FDIM + kk] = lo;
}

// ---------------- GEMM1 via mma.sync bf16 (split as K=768), BN=256 ----------
// Block 128x256, 16 warps (32x64 each), BK=32, cp.async double buffer.
// Fused att1: per-warp 64-col window = exactly 2 heads -> quad-reduced dots.
#define BM 128
#define BK 32
#define SSTR 40
#define NCH 24            // 768 / 32
#define A_BUF 10240       // 128*40*2 bytes
#define B_BUF 20480       // 256*40*2 bytes
#define GSMEM (2 * (A_BUF + B_BUF))   // 61440

__global__ void __launch_bounds__(512) k_gemm1_mma(const float* __restrict__ asrc,
                                                   const float* __restrict__ adst) {
    extern __shared__ char smem[];
    int tid = threadIdx.x, lane = tid & 31, wid = tid >> 5;
    int warpM = wid & 3, warpN = wid >> 2;    // 4 x 4 warps
    int bm = blockIdx.x * BM;

    uint32_t sb = smem_u32(smem);

    uint32_t a_off = (uint32_t)(((warpM * 32 + (lane & 15)) * SSTR + ((lane >> 4) << 3)) * 2);
    uint32_t b_off = (uint32_t)(((warpN * 64 + (lane & 7)) * SSTR + (((lane >> 3) & 1) << 3)) * 2);

    // cp.async coords: A 512 x 16B (1/thread), B 1024 x 16B (2/thread)
    int rowA = tid >> 2, segA = tid & 3;
    int grA  = min(bm + rowA, NN - 1);
    int rowB0 = tid >> 2,         segB0 = tid & 3;
    int rowB1 = (512 + tid) >> 2, segB1 = (512 + tid) & 3;

    float acc[2][8][4];
#pragma unroll
    for (int mt = 0; mt < 2; mt++)
#pragma unroll
        for (int nt = 0; nt < 8; nt++)
#pragma unroll
            for (int q = 0; q < 4; q++) acc[mt][nt][q] = 0.f;

    auto fill = [&](int c, int buf) {
        const __nv_bfloat16* Asrc = (c >= 8 && c < 16) ? g_xlo : g_xh;
        const __nv_bfloat16* Bsrc = (c < 16) ? g_wh : g_wlo;
        int kk = (c & 7) * BK;
        uint32_t ad = sb + buf * A_BUF;
        uint32_t bd = sb + 2 * A_BUF + buf * B_BUF;
        cpa16(ad + (rowA * SSTR + segA * 8) * 2,
              &Asrc[(size_t)grA * FDIM + kk + segA * 8]);
        cpa16(bd + (rowB0 * SSTR + segB0 * 8) * 2,
              &Bsrc[(size_t)rowB0 * FDIM + kk + segB0 * 8]);
        cpa16(bd + (rowB1 * SSTR + segB1 * 8) * 2,
              &Bsrc[(size_t)rowB1 * FDIM + kk + segB1 * 8]);
        asm volatile("cp.async.commit_group;" ::: "memory");
    };

    fill(0, 0);
    for (int c = 0; c < NCH; c++) {
        int buf = c & 1;
        if (c + 1 < NCH) {
            fill(c + 1, buf ^ 1);
            asm volatile("cp.async.wait_group 1;" ::: "memory");
        } else {
            asm volatile("cp.async.wait_group 0;" ::: "memory");
        }
        __syncthreads();

        uint32_t ab = sb + buf * A_BUF + a_off;
        uint32_t bb = sb + 2 * A_BUF + buf * B_BUF + b_off;
#pragma unroll
        for (int ks = 0; ks < 2; ks++) {
            uint32_t af[2][4];
            ldsm4(af[0], ab + (ks * 16) * 2);
            ldsm4(af[1], ab + (16 * SSTR + ks * 16) * 2);
            uint32_t bf[8][2];
#pragma unroll
            for (int nt = 0; nt < 8; nt++)
                ldsm2(bf[nt], bb + (nt * 8 * SSTR + ks * 16) * 2);
#pragma unroll
            for (int mt = 0; mt < 2; mt++)
#pragma unroll
                for (int nt = 0; nt < 8; nt++)
                    mma16816(acc[mt][nt], af[mt], bf[nt]);
        }
        __syncthreads();
    }

    // ---- epilogue: store g_xl + fused att1 dots ----
    int rbase = bm + warpM * 32 + (lane >> 2);
    int cbase = warpN * 64 + 2 * (lane & 3);
#pragma unroll
    for (int mt = 0; mt < 2; mt++) {
        int r0 = rbase + mt * 16;
#pragma unroll
        for (int nt = 0; nt < 8; nt++) {
            int cc = cbase + nt * 8;
            if (r0 < NN) {
                float2 v = make_float2(acc[mt][nt][0], acc[mt][nt][1]);
                *(float2*)&g_xl[(size_t)r0 * FDIM + cc] = v;
            }
            if (r0 + 8 < NN) {
                float2 v = make_float2(acc[mt][nt][2], acc[mt][nt][3]);
                *(float2*)&g_xl[(size_t)(r0 + 8) * FDIM + cc] = v;
            }
        }
    }

    // att1: heads h = warpN*2 + {0,1}; dot over this warp's 64-col window
    float ds[2][2][2], dd[2][2][2];   // [mt][half(row +0/+8)][head01]
#pragma unroll
    for (int mt = 0; mt < 2; mt++)
#pragma unroll
        for (int hf = 0; hf < 2; hf++)
#pragma unroll
            for (int hh = 0; hh < 2; hh++) { ds[mt][hf][hh] = 0.f; dd[mt][hf][hh] = 0.f; }
#pragma unroll
    for (int nt = 0; nt < 8; nt++) {
        int c0 = warpN * 64 + nt * 8 + 2 * (lane & 3);
        float s0 = __ldg(&asrc[c0]), s1 = __ldg(&asrc[c0 + 1]);
        float t0 = __ldg(&adst[c0]), t1 = __ldg(&adst[c0 + 1]);
        int hh = nt >> 2;
#pragma unroll
        for (int mt = 0; mt < 2; mt++)
#pragma unroll
            for (int hf = 0; hf < 2; hf++) {
                ds[mt][hf][hh] = fmaf(acc[mt][nt][hf * 2], s0,
                                 fmaf(acc[mt][nt][hf * 2 + 1], s1, ds[mt][hf][hh]));
                dd[mt][hf][hh] = fmaf(acc[mt][nt][hf * 2], t0,
                                 fmaf(acc[mt][nt][hf * 2 + 1], t1, dd[mt][hf][hh]));
            }
    }
#pragma unroll
    for (int mt = 0; mt < 2; mt++)
#pragma unroll
        for (int hf = 0; hf < 2; hf++)
#pragma unroll
            for (int hh = 0; hh < 2; hh++) {
                float v = ds[mt][hf][hh];
                v += __shfl_xor_sync(0xffffffffu, v, 1);
                v += __shfl_xor_sync(0xffffffffu, v, 2);
                ds[mt][hf][hh] = v;
                float u = dd[mt][hf][hh];
                u += __shfl_xor_sync(0xffffffffu, u, 1);
                u += __shfl_xor_sync(0xffffffffu, u, 2);
                dd[mt][hf][hh] = u;
            }
    if ((lane & 3) == 0) {
#pragma unroll
        for (int mt = 0; mt < 2; mt++)
#pragma unroll
            for (int hf = 0; hf < 2; hf++) {
                int row = rbase + hf * 8 + mt * 16;
                if (row < NN) {
                    g_as1[row * NHEAD + warpN * 2 + 0] = ds[mt][hf][0];
                    g_as1[row * NHEAD + warpN * 2 + 1] = ds[mt][hf][1];
                    g_ad1[row * NHEAD + warpN * 2 + 0] = dd[mt][hf][0];
                    g_ad1[row * NHEAD + warpN * 2 + 1] = dd[mt][hf][1];
                }
            }
    }
}

// ---------------- layer 1: fused softmax + aggregation (one warp per dst) ----
__global__ void __launch_bounds__(256) k_agg1() {
    int d = blockIdx.x * 8 + (threadIdx.x >> 5);
    int lane = threadIdx.x & 31;
    if (d >= NN) return;

    float ad = (lane < 8) ? g_ad1[d * NHEAD + lane] : 0.f;
    float wsum = 0.f;
    float4 accA = make_float4(0.f, 0.f, 0.f, 0.f);
    float4 accB = make_float4(0.f, 0.f, 0.f, 0.f);

    int beg = g_start[d];
    int end = beg + g_cnt[d];
    for (int p = beg - 1; p < end; p++) {       // p==beg-1 -> self loop
        int s = (p < beg) ? d : g_csrc[p];
        float w = 0.f;
        if (lane < 8) {
            float ev = g_as1[s * NHEAD + lane] + ad;
            ev = ev >= 0.f ? ev : 0.2f * ev;
            w = __expf(ev);
            wsum += w;
        }
        float aA = __shfl_sync(0xffffffffu, w, lane >> 3);        // head lane/8
        float aB = __shfl_sync(0xffffffffu, w, 4 + (lane >> 3));  // head 4+lane/8
        const float4* xs = (const float4*)&g_xl[(size_t)s * FDIM];
        float4 v1 = xs[lane];
        float4 v2 = xs[32 + lane];
        accA.x = fmaf(aA, v1.x, accA.x);
        accA.y = fmaf(aA, v1.y, accA.y);
        accA.z = fmaf(aA, v1.z, accA.z);
        accA.w = fmaf(aA, v1.w, accA.w);
        accB.x = fmaf(aB, v2.x, accB.x);
        accB.y = fmaf(aB, v2.y, accB.y);
        accB.z = fmaf(aB, v2.z, accB.z);
        accB.w = fmaf(aB, v2.w, accB.w);
    }
    float dA = __shfl_sync(0xffffffffu, wsum, lane >> 3);
    float dB = __shfl_sync(0xffffffffu, wsum, 4 + (lane >> 3));
    float rA = 1.f / (dA + 1e-16f);
    float rB = 1.f / (dB + 1e-16f);
    accA.x *= rA; accA.y *= rA; accA.z *= rA; accA.w *= rA;
    accB.x *= rB; accB.y *= rB; accB.z *= rB; accB.w *= rB;
    *(float4*)&g_out1[(size_t)d * FDIM + lane * 4] = accA;
    *(float4*)&g_out1[(size_t)d * FDIM + 128 + lane * 4] = accB;
}

// ---------------- layer 2: relu(out1+b1) @ W2, plus att2 dots ----------------
__global__ void __launch_bounds__(256) k_gemm2(const float* __restrict__ b1,
                                               const float* __restrict__ W2,
                                               const float* __restrict__ asrc2,
                                               const float* __restrict__ adst2) {
    __shared__ __align__(16) float W2s[FDIM * 17];   // padded stride 17
    __shared__ float b1s[FDIM];
    __shared__ __align__(16) float hs[8][FDIM];
    int tid = threadIdx.x;
#pragma unroll
    for (int i = 0; i < 16; i++) {
        int idx = i * 256 + tid;                     // 0..4095
        W2s[(idx >> 4) * 17 + (idx & 15)] = W2[idx];
    }
    b1s[tid] = b1[tid];
    __syncthreads();

    int w = tid >> 5, lane = tid & 31;
    int n = blockIdx.x * 8 + w;                      // grid = NN/8 exact
    {
        float4 v1 = *(const float4*)&g_out1[n * FDIM + lane * 4];
        const float* bp = &b1s[lane * 4];
        v1.x = fmaxf(v1.x + bp[0], 0.f);
        v1.y = fmaxf(v1.y + bp[1], 0.f);
        v1.z = fmaxf(v1.z + bp[2], 0.f);
        v1.w = fmaxf(v1.w + bp[3], 0.f);
        *(float4*)&hs[w][lane * 4] = v1;
        float4 v2 = *(const float4*)&g_out1[n * FDIM + 128 + lane * 4];
        const float* bq = &b1s[128 + lane * 4];
        v2.x = fmaxf(v2.x + bq[0], 0.f);
        v2.y = fmaxf(v2.y + bq[1], 0.f);
        v2.z = fmaxf(v2.z + bq[2], 0.f);
        v2.w = fmaxf(v2.w + bq[3], 0.f);
        *(float4*)&hs[w][128 + lane * 4] = v2;
    }
    __syncwarp();
    int c = lane & 15, half = lane >> 4;
    const float* hp = &hs[w][half * 128];
    const float* wp = &W2s[(half * 128) * 17 + c];
    float sum = 0.f;
#pragma unroll 16
    for (int k = 0; k < 128; k++) sum += hp[k] * wp[k * 17];
    sum += __shfl_xor_sync(0xffffffffu, sum, 16);
    if (lane < 16) g_y[n * OUTC + c] = sum;
    float ps = sum * __ldg(&asrc2[c]);
    float pd = sum * __ldg(&adst2[c]);
#pragma unroll
    for (int o = 8; o; o >>= 1) {
        ps += __shfl_xor_sync(0xffffffffu, ps, o);
        pd += __shfl_xor_sync(0xffffffffu, pd, o);
    }
    if (lane == 0) { g_as2[n] = ps; g_ad2[n] = pd; }
}

// ---------------- layer 2: fused softmax-agg + bias + log_softmax ------------
// One 16-lane half-warp per dst node.
__global__ void __launch_bounds__(256) k_agg2(float* __restrict__ dout,
                                              const float* __restrict__ b2) {
    int d = blockIdx.x * 16 + (threadIdx.x >> 4);
    int c = threadIdx.x & 15;
    if (d >= NN) return;

    float ad = g_ad2[d];
    float acc = 0.f, wsum = 0.f;
    int beg = g_start[d];
    int end = beg + g_cnt[d];
    for (int p = beg - 1; p < end; p++) {
        int s = (p < beg) ? d : g_csrc[p];
        float ev = g_as2[s] + ad;
        ev = ev >= 0.f ? ev : 0.2f * ev;
        float w = __expf(ev);
        wsum += w;
        acc = fmaf(w, g_y[s * OUTC + c], acc);
    }
    float v = acc / (wsum + 1e-16f) + __ldg(&b2[c]);

    float m = v;
#pragma unroll
    for (int o = 8; o; o >>= 1)
        m = fmaxf(m, __shfl_xor_sync(0xffffffffu, m, o, 16));
    float ex = __expf(v - m);
    float ssum = ex;
#pragma unroll
    for (int o = 8; o; o >>= 1)
        ssum += __shfl_xor_sync(0xffffffffu, ssum, o, 16);
    dout[d * OUTC + c] = v - m - __logf(ssum);
}

// ---------------- launch ----------------
extern "C" void kernel_launch(void* const* d_in, const int* in_sizes, int n_in,
                              void* d_out, int out_size) {
    const float* x     = (const float*)d_in[0];
    const void*  ei    = d_in[1];
    const float* W1    = (const float*)d_in[2];
    const float* asr1  = (const float*)d_in[3];
    const float* adr1  = (const float*)d_in[4];
    const float* b1    = (const float*)d_in[5];
    const float* W2    = (const float*)d_in[6];
    const float* asr2  = (const float*)d_in[7];
    const float* adr2  = (const float*)d_in[8];
    const float* b2    = (const float*)d_in[9];
    float* out = (float*)d_out;

    cudaFuncSetAttribute(k_gemm1_mma, cudaFuncAttributeMaxDynamicSharedMemorySize, GSMEM);

    k_detect<<<1, 32>>>((const unsigned*)ei);
    k_init<<<NBLK, 256>>>();
    k_convert_hist<<<(2 * EE + 255) / 256, 256>>>(ei);

    // CSR build
    k_scanA<<<NBLK, 256>>>();
    k_scanB<<<1, 256>>>();
    k_scanC<<<NBLK, 256>>>();
    k_scatter<<<(EE + 255) / 256, 256>>>();

    // bf16 split + GEMM1 (att1 fused into epilogue)
    k_cvt_x<<<(NN * FDIM / 4 + 255) / 256, 256>>>(x);
    k_cvt_w<<<(FDIM * FDIM / 2 + 255) / 256, 256>>>(W1);
    k_gemm1_mma<<<(NN + BM - 1) / BM, 512, GSMEM>>>(asr1, adr1);

    // layer 1 edge aggregation (gather-only)
    k_agg1<<<(NN + 7) / 8, 256>>>();

    // layer 2
    k_gemm2<<<NN / 8, 256>>>(b1, W2, asr2, adr2);
    k_agg2<<<(NN + 15) / 16, 256>>>(out, b2);
}

// round 12
// speedup vs baseline: 1.8396x; 1.0840x over previous
#include <cuda_runtime.h>
#include <cuda_bf16.h>
#include <cstdint>

#define NN   50000
#define EE   800000
#define FDIM 256
#define NHEAD 8
#define HID  32
#define OUTC 16
#define NBLK 196          // ceil(NN/256)

// ---------------- scratch (device globals; no allocation allowed) ----------------
__device__ __align__(16) int   g_ei[2 * EE];          // normalized int32 edge index
__device__ __align__(16) float g_xl[NN * FDIM];       // layer1 x @ W1
__device__ __align__(16) __nv_bfloat16 g_xh [NN * FDIM];   // bf16 hi of x
__device__ __align__(16) __nv_bfloat16 g_xlo[NN * FDIM];   // bf16 lo of x
__device__ __align__(16) __nv_bfloat16 g_wh [FDIM * FDIM]; // bf16 hi of W1^T [n][k]
__device__ __align__(16) __nv_bfloat16 g_wlo[FDIM * FDIM]; // bf16 lo of W1^T
__device__ __align__(16) float g_as1[NN * NHEAD];
__device__ __align__(16) float g_ad1[NN * NHEAD];
__device__ __align__(16) float g_y[NN * OUTC];        // layer2 h @ W2
__device__ __align__(16) float g_as2[NN];
__device__ __align__(16) float g_ad2[NN];
// CSR by dst (real edges only; self loop handled implicitly)
__device__ int g_cnt[NN];
__device__ int g_start[NN];
__device__ int g_cur[NN];
__device__ int g_csrc[EE];
__device__ int g_bsum[256];
__device__ int g_bpre[256];
__device__ int g_is64;

// ---------------- helpers ----------------
__device__ __forceinline__ uint32_t smem_u32(const void* p) {
    uint32_t a;
    asm("{ .reg .u64 t; cvta.to.shared.u64 t, %1; cvt.u32.u64 %0, t; }"
        : "=r"(a) : "l"(p));
    return a;
}
__device__ __forceinline__ void ldsm4(uint32_t* r, uint32_t addr) {
    asm volatile("ldmatrix.sync.aligned.m8n8.x4.shared.b16 {%0,%1,%2,%3}, [%4];"
                 : "=r"(r[0]), "=r"(r[1]), "=r"(r[2]), "=r"(r[3]) : "r"(addr));
}
__device__ __forceinline__ void ldsm2(uint32_t* r, uint32_t addr) {
    asm volatile("ldmatrix.sync.aligned.m8n8.x2.shared.b16 {%0,%1}, [%2];"
                 : "=r"(r[0]), "=r"(r[1]) : "r"(addr));
}
__device__ __forceinline__ void mma16816(float* d, const uint32_t* a, const uint32_t* b) {
    asm volatile("mma.sync.aligned.m16n8k16.row.col.f32.bf16.bf16.f32 "
                 "{%0,%1,%2,%3}, {%4,%5,%6,%7}, {%8,%9}, {%0,%1,%2,%3};"
                 : "+f"(d[0]), "+f"(d[1]), "+f"(d[2]), "+f"(d[3])
                 : "r"(a[0]), "r"(a[1]), "r"(a[2]), "r"(a[3]), "r"(b[0]), "r"(b[1]));
}
__device__ __forceinline__ void cpa16(uint32_t dst, const void* src) {
    asm volatile("cp.async.ca.shared.global [%0], [%1], 16;"
                 :: "r"(dst), "l"(src) : "memory");
}

// ---------------- setup kernels ----------------
__global__ void k_detect(const unsigned* ei) {
    if (blockIdx.x == 0 && threadIdx.x == 0) {
        int is64 = 1;
        for (int i = 0; i < 64; i++)
            if (ei[2 * i + 1] != 0u) { is64 = 0; break; }
        g_is64 = is64;
    }
}

__global__ void k_init() {
    int i = blockIdx.x * blockDim.x + threadIdx.x;
    if (i < NN) g_cnt[i] = 0;
}

// convert edge index to int32 AND histogram dst counts in one pass
__global__ void k_convert_hist(const void* ei) {
    int i = blockIdx.x * blockDim.x + threadIdx.x;
    if (i < 2 * EE) {
        int v = g_is64 ? (int)((const long long*)ei)[i]
                       : ((const int*)ei)[i];
        g_ei[i] = v;
        if (i >= EE) atomicAdd(&g_cnt[v], 1);
    }
}

// ---------------- CSR build: scan -> scatter ----------------
__global__ void k_scanA() {
    int i = blockIdx.x * 256 + threadIdx.x;
    int v = (i < NN) ? g_cnt[i] : 0;
#pragma unroll
    for (int o = 16; o; o >>= 1) v += __shfl_down_sync(0xffffffffu, v, o);
    __shared__ int s[8];
    if ((threadIdx.x & 31) == 0) s[threadIdx.x >> 5] = v;
    __syncthreads();
    if (threadIdx.x < 8) {
        int t = s[threadIdx.x];
#pragma unroll
        for (int o = 4; o; o >>= 1) t += __shfl_down_sync(0xffu, t, o);
        if (threadIdx.x == 0) g_bsum[blockIdx.x] = t;
    }
}
__global__ void k_scanB() {
    __shared__ int s[256];
    int t = threadIdx.x;
    int v = (t < NBLK) ? g_bsum[t] : 0;
    s[t] = v;
    __syncthreads();
    for (int o = 1; o < 256; o <<= 1) {
        int u = (t >= o) ? s[t - o] : 0;
        __syncthreads();
        s[t] += u;
        __syncthreads();
    }
    if (t < NBLK) g_bpre[t] = s[t] - v;
}
__global__ void k_scanC() {
    __shared__ int s[256];
    int t = threadIdx.x, i = blockIdx.x * 256 + t;
    int v = (i < NN) ? g_cnt[i] : 0;
    s[t] = v;
    __syncthreads();
    for (int o = 1; o < 256; o <<= 1) {
        int u = (t >= o) ? s[t - o] : 0;
        __syncthreads();
        s[t] += u;
        __syncthreads();
    }
    int excl = s[t] - v + g_bpre[blockIdx.x];
    if (i < NN) { g_start[i] = excl; g_cur[i] = excl; }
}
__global__ void k_scatter() {
    int e = blockIdx.x * blockDim.x + threadIdx.x;
    if (e < EE) {
        int d = g_ei[EE + e];
        int p = atomicAdd(&g_cur[d], 1);
        g_csrc[p] = g_ei[e];
    }
}

// ---------------- bf16 hi/lo split helpers ----------------
__device__ __forceinline__ void split2(float a, float b, unsigned& hi, unsigned& lo) {
    __nv_bfloat16 ha = __float2bfloat16(a), hb = __float2bfloat16(b);
    __nv_bfloat16 la = __float2bfloat16(a - __bfloat162float(ha));
    __nv_bfloat16 lb = __float2bfloat16(b - __bfloat162float(hb));
    __nv_bfloat162 H; H.x = ha; H.y = hb; hi = *(unsigned*)&H;
    __nv_bfloat162 L; L.x = la; L.y = lb; lo = *(unsigned*)&L;
}

__global__ void k_cvt_x(const float* __restrict__ x) {
    int i = blockIdx.x * blockDim.x + threadIdx.x;   // float4 index
    if (i >= NN * FDIM / 4) return;
    float4 v = ((const float4*)x)[i];
    uint2 H, L;
    split2(v.x, v.y, H.x, L.x);
    split2(v.z, v.w, H.y, L.y);
    ((uint2*)g_xh)[i]  = H;
    ((uint2*)g_xlo)[i] = L;
}

// W1 is [K=256, N=256] row-major; produce transposed [n][k] bf16 hi/lo.
__global__ void k_cvt_w(const float* __restrict__ W) {
    int idx = blockIdx.x * blockDim.x + threadIdx.x;  // 32768 threads
    if (idx >= FDIM * FDIM / 2) return;
    int n  = idx >> 7;
    int kk = (idx & 127) * 2;
    float v0 = W[kk * FDIM + n];
    float v1 = W[(kk + 1) * FDIM + n];
    unsigned hi, lo;
    split2(v0, v1, hi, lo);
    *(unsigned*)&g_wh [n * FDIM + kk] = hi;
    *(unsigned*)&g_wlo[n * FDIM + kk] = lo;
}

// ---------------- GEMM1 via mma.sync bf16 (split as K=768), BN=256 ----------
// Block 128x256, 16 warps (32x64 each), BK=32, cp.async double buffer.
// Fused att1: per-warp 64-col window = exactly 2 heads -> quad-reduced dots.
#define BM 128
#define BK 32
#define SSTR 40
#define NCH 24            // 768 / 32
#define A_BUF 10240       // 128*40*2 bytes
#define B_BUF 20480       // 256*40*2 bytes
#define GSMEM (2 * (A_BUF + B_BUF))   // 61440

__global__ void __launch_bounds__(512) k_gemm1_mma(const float* __restrict__ asrc,
                                                   const float* __restrict__ adst) {
    extern __shared__ char smem[];
    int tid = threadIdx.x, lane = tid & 31, wid = tid >> 5;
    int warpM = wid & 3, warpN = wid >> 2;    // 4 x 4 warps
    int bm = blockIdx.x * BM;

    uint32_t sb = smem_u32(smem);

    uint32_t a_off = (uint32_t)(((warpM * 32 + (lane & 15)) * SSTR + ((lane >> 4) << 3)) * 2);
    uint32_t b_off = (uint32_t)(((warpN * 64 + (lane & 7)) * SSTR + (((lane >> 3) & 1) << 3)) * 2);

    // cp.async coords: A 512 x 16B (1/thread), B 1024 x 16B (2/thread)
    int rowA = tid >> 2, segA = tid & 3;
    int grA  = min(bm + rowA, NN - 1);
    int rowB0 = tid >> 2,         segB0 = tid & 3;
    int rowB1 = (512 + tid) >> 2, segB1 = (512 + tid) & 3;

    float acc[2][8][4];
#pragma unroll
    for (int mt = 0; mt < 2; mt++)
#pragma unroll
        for (int nt = 0; nt < 8; nt++)
#pragma unroll
            for (int q = 0; q < 4; q++) acc[mt][nt][q] = 0.f;

    auto fill = [&](int c, int buf) {
        const __nv_bfloat16* Asrc = (c >= 8 && c < 16) ? g_xlo : g_xh;
        const __nv_bfloat16* Bsrc = (c < 16) ? g_wh : g_wlo;
        int kk = (c & 7) * BK;
        uint32_t ad = sb + buf * A_BUF;
        uint32_t bd = sb + 2 * A_BUF + buf * B_BUF;
        cpa16(ad + (rowA * SSTR + segA * 8) * 2,
              &Asrc[(size_t)grA * FDIM + kk + segA * 8]);
        cpa16(bd + (rowB0 * SSTR + segB0 * 8) * 2,
              &Bsrc[(size_t)rowB0 * FDIM + kk + segB0 * 8]);
        cpa16(bd + (rowB1 * SSTR + segB1 * 8) * 2,
              &Bsrc[(size_t)rowB1 * FDIM + kk + segB1 * 8]);
        asm volatile("cp.async.commit_group;" ::: "memory");
    };

    fill(0, 0);
    for (int c = 0; c < NCH; c++) {
        int buf = c & 1;
        if (c + 1 < NCH) {
            fill(c + 1, buf ^ 1);
            asm volatile("cp.async.wait_group 1;" ::: "memory");
        } else {
            asm volatile("cp.async.wait_group 0;" ::: "memory");
        }
        __syncthreads();

        uint32_t ab = sb + buf * A_BUF + a_off;
        uint32_t bb = sb + 2 * A_BUF + buf * B_BUF + b_off;
#pragma unroll
        for (int ks = 0; ks < 2; ks++) {
            uint32_t af[2][4];
            ldsm4(af[0], ab + (ks * 16) * 2);
            ldsm4(af[1], ab + (16 * SSTR + ks * 16) * 2);
            uint32_t bf[8][2];
#pragma unroll
            for (int nt = 0; nt < 8; nt++)
                ldsm2(bf[nt], bb + (nt * 8 * SSTR + ks * 16) * 2);
#pragma unroll
            for (int mt = 0; mt < 2; mt++)
#pragma unroll
                for (int nt = 0; nt < 8; nt++)
                    mma16816(acc[mt][nt], af[mt], bf[nt]);
        }
        __syncthreads();
    }

    // ---- epilogue: store g_xl + fused att1 dots ----
    int rbase = bm + warpM * 32 + (lane >> 2);
    int cbase = warpN * 64 + 2 * (lane & 3);
#pragma unroll
    for (int mt = 0; mt < 2; mt++) {
        int r0 = rbase + mt * 16;
#pragma unroll
        for (int nt = 0; nt < 8; nt++) {
            int cc = cbase + nt * 8;
            if (r0 < NN) {
                float2 v = make_float2(acc[mt][nt][0], acc[mt][nt][1]);
                *(float2*)&g_xl[(size_t)r0 * FDIM + cc] = v;
            }
            if (r0 + 8 < NN) {
                float2 v = make_float2(acc[mt][nt][2], acc[mt][nt][3]);
                *(float2*)&g_xl[(size_t)(r0 + 8) * FDIM + cc] = v;
            }
        }
    }

    // att1: heads h = warpN*2 + {0,1}; dot over this warp's 64-col window
    float ds[2][2][2], dd[2][2][2];   // [mt][half(row +0/+8)][head01]
#pragma unroll
    for (int mt = 0; mt < 2; mt++)
#pragma unroll
        for (int hf = 0; hf < 2; hf++)
#pragma unroll
            for (int hh = 0; hh < 2; hh++) { ds[mt][hf][hh] = 0.f; dd[mt][hf][hh] = 0.f; }
#pragma unroll
    for (int nt = 0; nt < 8; nt++) {
        int c0 = warpN * 64 + nt * 8 + 2 * (lane & 3);
        float s0 = __ldg(&asrc[c0]), s1 = __ldg(&asrc[c0 + 1]);
        float t0 = __ldg(&adst[c0]), t1 = __ldg(&adst[c0 + 1]);
        int hh = nt >> 2;
#pragma unroll
        for (int mt = 0; mt < 2; mt++)
#pragma unroll
            for (int hf = 0; hf < 2; hf++) {
                ds[mt][hf][hh] = fmaf(acc[mt][nt][hf * 2], s0,
                                 fmaf(acc[mt][nt][hf * 2 + 1], s1, ds[mt][hf][hh]));
                dd[mt][hf][hh] = fmaf(acc[mt][nt][hf * 2], t0,
                                 fmaf(acc[mt][nt][hf * 2 + 1], t1, dd[mt][hf][hh]));
            }
    }
#pragma unroll
    for (int mt = 0; mt < 2; mt++)
#pragma unroll
        for (int hf = 0; hf < 2; hf++)
#pragma unroll
            for (int hh = 0; hh < 2; hh++) {
                float v = ds[mt][hf][hh];
                v += __shfl_xor_sync(0xffffffffu, v, 1);
                v += __shfl_xor_sync(0xffffffffu, v, 2);
                ds[mt][hf][hh] = v;
                float u = dd[mt][hf][hh];
                u += __shfl_xor_sync(0xffffffffu, u, 1);
                u += __shfl_xor_sync(0xffffffffu, u, 2);
                dd[mt][hf][hh] = u;
            }
    if ((lane & 3) == 0) {
#pragma unroll
        for (int mt = 0; mt < 2; mt++)
#pragma unroll
            for (int hf = 0; hf < 2; hf++) {
                int row = rbase + hf * 8 + mt * 16;
                if (row < NN) {
                    g_as1[row * NHEAD + warpN * 2 + 0] = ds[mt][hf][0];
                    g_as1[row * NHEAD + warpN * 2 + 1] = ds[mt][hf][1];
                    g_ad1[row * NHEAD + warpN * 2 + 0] = dd[mt][hf][0];
                    g_ad1[row * NHEAD + warpN * 2 + 1] = dd[mt][hf][1];
                }
            }
    }
}

// ---------------- layer 1 agg + relu/bias + GEMM2 + att2, all fused ----------
// One warp per dst node; 8 dsts per 256-thread CTA.
__global__ void __launch_bounds__(256) k_agg1f(const float* __restrict__ b1,
                                               const float* __restrict__ W2,
                                               const float* __restrict__ asrc2,
                                               const float* __restrict__ adst2) {
    __shared__ __align__(16) float W2s[FDIM * 17];   // padded stride 17
    __shared__ float b1s[FDIM];
    __shared__ __align__(16) float hs[8][FDIM];
    int tid = threadIdx.x;
#pragma unroll
    for (int i = 0; i < 16; i++) {
        int idx = i * 256 + tid;                     // 0..4095
        W2s[(idx >> 4) * 17 + (idx & 15)] = W2[idx];
    }
    b1s[tid] = b1[tid];
    __syncthreads();

    int w = tid >> 5, lane = tid & 31;
    int d = blockIdx.x * 8 + w;                      // grid = NN/8 exact
    if (d >= NN) return;

    // ---- edge aggregation (softmax over in-edges + self loop) ----
    float ad = (lane < 8) ? g_ad1[d * NHEAD + lane] : 0.f;
    float wsum = 0.f;
    float4 accA = make_float4(0.f, 0.f, 0.f, 0.f);
    float4 accB = make_float4(0.f, 0.f, 0.f, 0.f);

    int beg = g_start[d];
    int end = beg + g_cnt[d];
    for (int p = beg - 1; p < end; p++) {       // p==beg-1 -> self loop
        int s = (p < beg) ? d : g_csrc[p];
        float wgt = 0.f;
        if (lane < 8) {
            float ev = g_as1[s * NHEAD + lane] + ad;
            ev = ev >= 0.f ? ev : 0.2f * ev;
            wgt = __expf(ev);
            wsum += wgt;
        }
        float aA = __shfl_sync(0xffffffffu, wgt, lane >> 3);        // head lane/8
        float aB = __shfl_sync(0xffffffffu, wgt, 4 + (lane >> 3));  // head 4+lane/8
        const float4* xs = (const float4*)&g_xl[(size_t)s * FDIM];
        float4 v1 = xs[lane];
        float4 v2 = xs[32 + lane];
        accA.x = fmaf(aA, v1.x, accA.x);
        accA.y = fmaf(aA, v1.y, accA.y);
        accA.z = fmaf(aA, v1.z, accA.z);
        accA.w = fmaf(aA, v1.w, accA.w);
        accB.x = fmaf(aB, v2.x, accB.x);
        accB.y = fmaf(aB, v2.y, accB.y);
        accB.z = fmaf(aB, v2.z, accB.z);
        accB.w = fmaf(aB, v2.w, accB.w);
    }
    float dA = __shfl_sync(0xffffffffu, wsum, lane >> 3);
    float dB = __shfl_sync(0xffffffffu, wsum, 4 + (lane >> 3));
    float rA = 1.f / (dA + 1e-16f);
    float rB = 1.f / (dB + 1e-16f);

    // ---- relu(out1 + b1) -> smem row ----
    {
        const float* bp = &b1s[lane * 4];
        float4 h1;
        h1.x = fmaxf(accA.x * rA + bp[0], 0.f);
        h1.y = fmaxf(accA.y * rA + bp[1], 0.f);
        h1.z = fmaxf(accA.z * rA + bp[2], 0.f);
        h1.w = fmaxf(accA.w * rA + bp[3], 0.f);
        *(float4*)&hs[w][lane * 4] = h1;
        const float* bq = &b1s[128 + lane * 4];
        float4 h2;
        h2.x = fmaxf(accB.x * rB + bq[0], 0.f);
        h2.y = fmaxf(accB.y * rB + bq[1], 0.f);
        h2.z = fmaxf(accB.z * rB + bq[2], 0.f);
        h2.w = fmaxf(accB.w * rB + bq[3], 0.f);
        *(float4*)&hs[w][128 + lane * 4] = h2;
    }
    __syncwarp();

    // ---- GEMM2 dot: y[c] = sum_k h[k] * W2[k][c] ----
    int c = lane & 15, half = lane >> 4;
    const float* hp = &hs[w][half * 128];
    const float* wp = &W2s[(half * 128) * 17 + c];
    float sum = 0.f;
#pragma unroll 16
    for (int k = 0; k < 128; k++) sum += hp[k] * wp[k * 17];
    sum += __shfl_xor_sync(0xffffffffu, sum, 16);
    if (lane < 16) g_y[d * OUTC + c] = sum;

    // ---- att2 dots ----
    float ps = sum * __ldg(&asrc2[c]);
    float pd = sum * __ldg(&adst2[c]);
#pragma unroll
    for (int o = 8; o; o >>= 1) {
        ps += __shfl_xor_sync(0xffffffffu, ps, o);
        pd += __shfl_xor_sync(0xffffffffu, pd, o);
    }
    if (lane == 0) { g_as2[d] = ps; g_ad2[d] = pd; }
}

// ---------------- layer 2: fused softmax-agg + bias + log_softmax ------------
// One 16-lane half-warp per dst node.
__global__ void __launch_bounds__(256) k_agg2(float* __restrict__ dout,
                                              const float* __restrict__ b2) {
    int d = blockIdx.x * 16 + (threadIdx.x >> 4);
    int c = threadIdx.x & 15;
    if (d >= NN) return;

    float ad = g_ad2[d];
    float acc = 0.f, wsum = 0.f;
    int beg = g_start[d];
    int end = beg + g_cnt[d];
    for (int p = beg - 1; p < end; p++) {
        int s = (p < beg) ? d : g_csrc[p];
        float ev = g_as2[s] + ad;
        ev = ev >= 0.f ? ev : 0.2f * ev;
        float w = __expf(ev);
        wsum += w;
        acc = fmaf(w, g_y[s * OUTC + c], acc);
    }
    float v = acc / (wsum + 1e-16f) + __ldg(&b2[c]);

    float m = v;
#pragma unroll
    for (int o = 8; o; o >>= 1)
        m = fmaxf(m, __shfl_xor_sync(0xffffffffu, m, o, 16));
    float ex = __expf(v - m);
    float ssum = ex;
#pragma unroll
    for (int o = 8; o; o >>= 1)
        ssum += __shfl_xor_sync(0xffffffffu, ssum, o, 16);
    dout[d * OUTC + c] = v - m - __logf(ssum);
}

// ---------------- launch ----------------
extern "C" void kernel_launch(void* const* d_in, const int* in_sizes, int n_in,
                              void* d_out, int out_size) {
    const float* x     = (const float*)d_in[0];
    const void*  ei    = d_in[1];
    const float* W1    = (const float*)d_in[2];
    const float* asr1  = (const float*)d_in[3];
    const float* adr1  = (const float*)d_in[4];
    const float* b1    = (const float*)d_in[5];
    const float* W2    = (const float*)d_in[6];
    const float* asr2  = (const float*)d_in[7];
    const float* adr2  = (const float*)d_in[8];
    const float* b2    = (const float*)d_in[9];
    float* out = (float*)d_out;

    cudaFuncSetAttribute(k_gemm1_mma, cudaFuncAttributeMaxDynamicSharedMemorySize, GSMEM);

    k_detect<<<1, 32>>>((const unsigned*)ei);
    k_init<<<NBLK, 256>>>();
    k_convert_hist<<<(2 * EE + 255) / 256, 256>>>(ei);

    // CSR build
    k_scanA<<<NBLK, 256>>>();
    k_scanB<<<1, 256>>>();
    k_scanC<<<NBLK, 256>>>();
    k_scatter<<<(EE + 255) / 256, 256>>>();

    // bf16 split + GEMM1 (att1 fused into epilogue)
    k_cvt_x<<<(NN * FDIM / 4 + 255) / 256, 256>>>(x);
    k_cvt_w<<<(FDIM * FDIM / 2 + 255) / 256, 256>>>(W1);
    k_gemm1_mma<<<(NN + BM - 1) / BM, 512, GSMEM>>>(asr1, adr1);

    // layer 1 aggregation fused with relu/bias + GEMM2 + att2
    k_agg1f<<<(NN + 7) / 8, 256>>>(b1, W2, asr2, adr2);

    // layer 2 aggregation + log_softmax
    k_agg2<<<(NN + 15) / 16, 256>>>(out, b2);
}